// round 1
// baseline (speedup 1.0000x reference)
#include <cuda_runtime.h>
#include <math.h>

#define NB    256      // batch
#define NM    6        // goals
#define INC   448
#define EMB   32
#define NHEAD 8
#define DFF   2048
#define OBS   20
#define HOR   30
#define DD    512      // model dim
#define LBUF  50
#define HD    64
#define HH    448      // fusion hidden
#define BMT   1536     // NB*NM

// ------------------------- scratch (static device globals) -------------------------
__device__ __align__(256) float g_cfeat[NB*1536];      // feat @ W_qkv[64:512] + b_qkv
__device__ __align__(256) float g_cffus[NB*448];       // feat @ W_fus[519:967] + b_fus
__device__ __align__(256) float g_Wcat[64*1536];       // [extras rows; emb rows (q cols only)]
__device__ __align__(256) float g_eKV[(size_t)LBUF*BMT*1024]; // per-frame emb contribution to k|v
__device__ __align__(256) float g_E[BMT*64];           // [extras(32) | embPrev(32)]
__device__ __align__(256) float g_xlast[BMT*DD];
__device__ __align__(256) float g_rowfus[BMT*448];
__device__ __align__(256) float g_QKVC[BMT*1536];      // q | ck | cv
__device__ __align__(256) float g_ctx[BMT*DD];
__device__ __align__(256) float g_wo[BMT*DD];
__device__ __align__(256) float g_h1[BMT*DD];
__device__ __align__(256) float g_ff1[BMT*DFF];
__device__ __align__(256) float g_ff2[BMT*DD];
__device__ __align__(256) float g_h2[BMT*DD];
__device__ __align__(256) float g_fus[BMT*448];
__device__ __align__(256) float g_emb[BMT*EMB];        // emb of frame f-1
__device__ __align__(256) float g_last[BMT*2];

// ------------------------- generic fp32 GEMM: C = A@B (+bias)(+rowadd)(relu) ------
// 64x64 tile, BK=16, 256 threads, 4x4 microtile. M,N must be multiples of 64,
// K a multiple of 16, all lds multiples of 4.
__global__ void k_gemm(const float* __restrict__ A, int lda,
                       const float* __restrict__ Bm, int ldb,
                       float* __restrict__ C, int ldc,
                       int K,
                       const float* __restrict__ bias,
                       const float* __restrict__ rowadd, int ramod, int ldra,
                       int relu)
{
    __shared__ __align__(16) float As[16][64];
    __shared__ __align__(16) float Bs[16][64];
    const int row0 = blockIdx.y * 64, col0 = blockIdx.x * 64;
    const int tid = threadIdx.x;
    const int tx = tid & 15, ty = tid >> 4;
    const int ar = tid >> 2, ak = (tid & 3) << 2;
    const int bk = tid >> 4, bc = (tid & 15) << 2;
    float acc[4][4] = {};
    for (int k0 = 0; k0 < K; k0 += 16) {
        float4 a4 = *(const float4*)(A + (size_t)(row0 + ar) * lda + k0 + ak);
        As[ak + 0][ar] = a4.x;
        As[ak + 1][ar] = a4.y;
        As[ak + 2][ar] = a4.z;
        As[ak + 3][ar] = a4.w;
        *(float4*)&Bs[bk][bc] = *(const float4*)(Bm + (size_t)(k0 + bk) * ldb + col0 + bc);
        __syncthreads();
#pragma unroll
        for (int kk = 0; kk < 16; kk++) {
            float4 a = *(const float4*)&As[kk][ty * 4];
            float4 b = *(const float4*)&Bs[kk][tx * 4];
            acc[0][0] += a.x * b.x; acc[0][1] += a.x * b.y; acc[0][2] += a.x * b.z; acc[0][3] += a.x * b.w;
            acc[1][0] += a.y * b.x; acc[1][1] += a.y * b.y; acc[1][2] += a.y * b.z; acc[1][3] += a.y * b.w;
            acc[2][0] += a.z * b.x; acc[2][1] += a.z * b.y; acc[2][2] += a.z * b.z; acc[2][3] += a.z * b.w;
            acc[3][0] += a.w * b.x; acc[3][1] += a.w * b.y; acc[3][2] += a.w * b.z; acc[3][3] += a.w * b.w;
        }
        __syncthreads();
    }
    const int r = row0 + ty * 4, c = col0 + tx * 4;
#pragma unroll
    for (int i = 0; i < 4; i++) {
        const float* ra = rowadd ? (rowadd + (size_t)((r + i) % ramod) * ldra + c) : (const float*)0;
#pragma unroll
        for (int j = 0; j < 4; j++) {
            float v = acc[i][j];
            if (bias) v += bias[c + j];
            if (ra)   v += ra[j];
            if (relu) v = fmaxf(v, 0.f);
            C[(size_t)(r + i) * ldc + c + j] = v;
        }
    }
}

// ------------------------- one-time: build Wcat (64 x 1536) -----------------------
// rows 0..31 = W_qkv rows 32..63 (extras, all cols); rows 32..63 = W_qkv rows 0..31
// (emb contribution, only q columns — k/v emb parts live in the eKV cache).
__global__ void k_wcat(const float* __restrict__ Wqkv)
{
    int i = blockIdx.x * blockDim.x + threadIdx.x;
    if (i >= 64 * 1536) return;
    int r = i / 1536, c = i - r * 1536;
    float v;
    if (r < 32) v = Wqkv[(32 + r) * 1536 + c];
    else        v = (c < 512) ? Wqkv[(r - 32) * 1536 + c] : 0.f;
    g_Wcat[i] = v;
}

// ------------------------- one-time: obs frames -> eKV, init emb/last -------------
__global__ void k_p1(const float* __restrict__ obs, const float* __restrict__ Wemb,
                     const float* __restrict__ bemb, const float* __restrict__ Wqkv)
{
    int bm = blockIdx.x, l = blockIdx.y, tid = threadIdx.x;
    int b = bm & 255;
    __shared__ float se[32];
    if (tid < 32) {
        float o0 = obs[(l * NB + b) * 2 + 0];
        float o1 = obs[(l * NB + b) * 2 + 1];
        se[tid] = fmaxf(o0 * Wemb[tid] + o1 * Wemb[32 + tid] + bemb[tid], 0.f);
    }
    __syncthreads();
    float* dst = g_eKV + ((size_t)l * BMT + bm) * 1024;
    for (int c = tid; c < 1024; c += 128) {
        float acc = 0.f;
#pragma unroll
        for (int e = 0; e < 32; e++) acc += se[e] * Wqkv[e * 1536 + 512 + c];
        dst[c] = acc;
    }
    if (l == OBS - 1) {
        if (tid < 32) g_emb[bm * 32 + tid] = se[tid];
        if (tid < 2)  g_last[bm * 2 + tid] = obs[((OBS - 1) * NB + b) * 2 + tid];
    }
}

// ------------------------- per-step: extras / E / xlast / rowfus ------------------
__global__ void k_prep(const float* __restrict__ loc, const float* __restrict__ feat,
                       const float* __restrict__ Wfus, int f)
{
    int bm = blockIdx.x, tid = threadIdx.x;
    int b = bm & 255, m = bm >> 8;
    float gx = loc[(b * NM + m) * 2 + 0], gy = loc[(b * NM + m) * 2 + 1];
    float lx = g_last[bm * 2 + 0], ly = g_last[bm * 2 + 1];
    float dx = gx - lx, dy = gy - ly;
    float t = (float)f;
    __shared__ float ex[32];
    if (tid < 32) {
        float v;
        if (tid < 8)       v = (tid & 1) ? gy : gx;
        else if (tid < 16) v = (tid & 1) ? ly : lx;
        else if (tid < 24) v = (tid & 1) ? dy : dx;
        else               v = t;
        ex[tid] = v;
        g_E[bm * 64 + tid] = v;
        g_E[bm * 64 + 32 + tid] = g_emb[bm * 32 + tid];
    }
    __syncthreads();
    for (int c = tid; c < 512; c += 128) {
        float v;
        if (c < 32)      v = g_emb[bm * 32 + c];
        else if (c < 64) v = ex[c - 32];
        else             v = feat[b * INC + (c - 64)];
        g_xlast[bm * 512 + c] = v;
    }
    for (int c = tid; c < 448; c += 128) {
        float v = g_cffus[b * 448 + c];
        v += lx * Wfus[(512 + 0) * 448 + c];
        v += ly * Wfus[(512 + 1) * 448 + c];
        v += gx * Wfus[(512 + 2) * 448 + c];
        v += gy * Wfus[(512 + 3) * 448 + c];
        v += dx * Wfus[(512 + 4) * 448 + c];
        v += dy * Wfus[(512 + 5) * 448 + c];
        v += t  * Wfus[(512 + 6) * 448 + c];
        g_rowfus[bm * 448 + c] = v;
    }
}

// ------------------------- per-step attention (one block per bm, warp per head) ---
__global__ void k_attn(int f)
{
    int bm = blockIdx.x;
    int tid = threadIdx.x, w = tid >> 5, lane = tid & 31;
    const float* qp = g_QKVC + (size_t)bm * 1536 + w * 64;
    float q0 = qp[lane], q1 = qp[lane + 32];
    const float* ckp = qp + 512;
    float s = q0 * ckp[lane] + q1 * ckp[lane + 32];
#pragma unroll
    for (int o = 16; o; o >>= 1) s += __shfl_xor_sync(0xffffffffu, s, o);
    const float qdot = s;
    __shared__ float sp[8][56];
    const float* kbase = g_eKV + (size_t)bm * 1024 + w * 64;
    for (int l = 0; l < f; l++) {
        const float* kp = kbase + (size_t)l * BMT * 1024;
        float d = q0 * kp[lane] + q1 * kp[lane + 32];
#pragma unroll
        for (int o = 16; o; o >>= 1) d += __shfl_xor_sync(0xffffffffu, d, o);
        if (lane == 0) sp[w][l] = (d + qdot) * 0.125f;
    }
    __syncwarp();
    float mx = -1e30f;
    if (lane < f)      mx = sp[w][lane];
    if (lane + 32 < f) mx = fmaxf(mx, sp[w][lane + 32]);
#pragma unroll
    for (int o = 16; o; o >>= 1) mx = fmaxf(mx, __shfl_xor_sync(0xffffffffu, mx, o));
    float e0 = 0.f, e1 = 0.f;
    if (lane < f)      e0 = expf(sp[w][lane] - mx);
    if (lane + 32 < f) e1 = expf(sp[w][lane + 32] - mx);
    float sum = e0 + e1;
#pragma unroll
    for (int o = 16; o; o >>= 1) sum += __shfl_xor_sync(0xffffffffu, sum, o);
    if (lane < f)      sp[w][lane] = e0;
    if (lane + 32 < f) sp[w][lane + 32] = e1;
    __syncwarp();
    float inv = 1.f / sum;
    const float* cvp = qp + 1024;
    const float* vbase = kbase + 512;
    float a0 = 0.f, a1 = 0.f;
    for (int l = 0; l < f; l++) {
        float p = sp[w][l];
        const float* vp = vbase + (size_t)l * BMT * 1024;
        a0 += p * vp[lane];
        a1 += p * vp[lane + 32];
    }
    g_ctx[(size_t)bm * 512 + w * 64 + lane]      = cvp[lane]      + a0 * inv;
    g_ctx[(size_t)bm * 512 + w * 64 + lane + 32] = cvp[lane + 32] + a1 * inv;
}

// ------------------------- layernorm over 512: out = LN(x1+x2)*g+b ----------------
__global__ void k_ln(const float* __restrict__ x1, const float* __restrict__ x2,
                     const float* __restrict__ g, const float* __restrict__ bb,
                     float* __restrict__ out)
{
    int row = blockIdx.x, tid = threadIdx.x;
    __shared__ float red[256];
    float v0 = x1[(size_t)row * 512 + tid]       + x2[(size_t)row * 512 + tid];
    float v1 = x1[(size_t)row * 512 + tid + 256] + x2[(size_t)row * 512 + tid + 256];
    red[tid] = v0 + v1;
    __syncthreads();
    for (int s = 128; s; s >>= 1) { if (tid < s) red[tid] += red[tid + s]; __syncthreads(); }
    float mu = red[0] * (1.f / 512.f);
    __syncthreads();
    float d0 = v0 - mu, d1 = v1 - mu;
    red[tid] = d0 * d0 + d1 * d1;
    __syncthreads();
    for (int s = 128; s; s >>= 1) { if (tid < s) red[tid] += red[tid + s]; __syncthreads(); }
    float rs = rsqrtf(red[0] * (1.f / 512.f) + 1e-5f);
    out[(size_t)row * 512 + tid]       = d0 * rs * g[tid] + bb[tid];
    out[(size_t)row * 512 + tid + 256] = d1 * rs * g[tid + 256] + bb[tid + 256];
}

// ------------------------- per-step epilogue: out, write, emb update --------------
__global__ void k_finish(const float* __restrict__ Wout, const float* __restrict__ bout,
                         const float* __restrict__ Wemb, const float* __restrict__ bemb,
                         float* __restrict__ dout, int f)
{
    int bm = blockIdx.x, tid = threadIdx.x;
    int b = bm & 255, m = bm >> 8;
    __shared__ float r0[128], r1[128];
    float s0 = 0.f, s1 = 0.f;
    const float* fp = g_fus + (size_t)bm * 448;
    for (int c = tid; c < 448; c += 128) {
        float v = fp[c];
        s0 += v * Wout[c * 2 + 0];
        s1 += v * Wout[c * 2 + 1];
    }
    r0[tid] = s0; r1[tid] = s1;
    __syncthreads();
    for (int s = 64; s; s >>= 1) {
        if (tid < s) { r0[tid] += r0[tid + s]; r1[tid] += r1[tid + s]; }
        __syncthreads();
    }
    float o0 = r0[0] + bout[0];
    float o1 = r1[0] + bout[1];
    if (tid < 32) {
        float e = o0 * Wemb[tid] + o1 * Wemb[32 + tid] + bemb[tid];
        g_emb[bm * 32 + tid] = fmaxf(e, 0.f);
    }
    if (tid == 0) {
        g_last[bm * 2 + 0] = o0;
        g_last[bm * 2 + 1] = o1;
        int t = f - OBS;
        dout[b * (NM * HOR * 2) + m * (HOR * 2) + t * 2 + 0] = o0;
        dout[b * (NM * HOR * 2) + m * (HOR * 2) + t * 2 + 1] = o1;
    }
}

// ----------------------------------- launch ---------------------------------------
extern "C" void kernel_launch(void* const* d_in, const int* in_sizes, int n_in,
                              void* d_out, int out_size)
{
    const float* feat = (const float*)d_in[0];
    const float* loc  = (const float*)d_in[1];
    const float* obs  = (const float*)d_in[2];
    const float* Wemb = (const float*)d_in[3];
    const float* bemb = (const float*)d_in[4];
    const float* Wqkv = (const float*)d_in[5];
    const float* bqkv = (const float*)d_in[6];
    const float* Wo   = (const float*)d_in[7];
    const float* bo   = (const float*)d_in[8];
    const float* Wff1 = (const float*)d_in[9];
    const float* bff1 = (const float*)d_in[10];
    const float* bff2 = (const float*)d_in[12];
    const float* Wff2 = (const float*)d_in[11];
    const float* ln1g = (const float*)d_in[13];
    const float* ln1b = (const float*)d_in[14];
    const float* ln2g = (const float*)d_in[15];
    const float* ln2b = (const float*)d_in[16];
    const float* Wfus = (const float*)d_in[17];
    const float* bfus = (const float*)d_in[18];
    const float* Wout = (const float*)d_in[19];
    const float* bout = (const float*)d_in[20];
    float* outp = (float*)d_out;

    float *cfeat, *cffus, *Wcat, *eKV, *E, *xlast, *rowfus, *QKVC, *ctx, *wo,
          *h1, *ff1, *ff2, *h2, *fus, *emb;
    cudaGetSymbolAddress((void**)&cfeat,  g_cfeat);
    cudaGetSymbolAddress((void**)&cffus,  g_cffus);
    cudaGetSymbolAddress((void**)&Wcat,   g_Wcat);
    cudaGetSymbolAddress((void**)&eKV,    g_eKV);
    cudaGetSymbolAddress((void**)&E,      g_E);
    cudaGetSymbolAddress((void**)&xlast,  g_xlast);
    cudaGetSymbolAddress((void**)&rowfus, g_rowfus);
    cudaGetSymbolAddress((void**)&QKVC,   g_QKVC);
    cudaGetSymbolAddress((void**)&ctx,    g_ctx);
    cudaGetSymbolAddress((void**)&wo,     g_wo);
    cudaGetSymbolAddress((void**)&h1,     g_h1);
    cudaGetSymbolAddress((void**)&ff1,    g_ff1);
    cudaGetSymbolAddress((void**)&ff2,    g_ff2);
    cudaGetSymbolAddress((void**)&h2,     g_h2);
    cudaGetSymbolAddress((void**)&fus,    g_fus);
    cudaGetSymbolAddress((void**)&emb,    g_emb);

    // one-time precompute (inside the graph; cheap + deterministic)
    k_wcat<<<(64 * 1536 + 255) / 256, 256>>>(Wqkv);
    // cfeat = feat @ W_qkv[64:512,:] + b_qkv   (256 x 1536, K=448)
    k_gemm<<<dim3(1536 / 64, NB / 64), 256>>>(feat, 448, Wqkv + 64 * 1536, 1536,
                                              cfeat, 1536, 448, bqkv, (const float*)0, 1, 0, 0);
    // cffus = feat @ W_fus[519:967,:] + b_fus  (256 x 448, K=448)
    k_gemm<<<dim3(448 / 64, NB / 64), 256>>>(feat, 448, Wfus + 519 * 448, 448,
                                             cffus, 448, 448, bfus, (const float*)0, 1, 0, 0);
    k_p1<<<dim3(BMT, OBS), 128>>>(obs, Wemb, bemb, Wqkv);

    for (int f = OBS; f < OBS + HOR; f++) {
        k_prep<<<BMT, 128>>>(loc, feat, Wfus, f);
        // QKVC = E @ Wcat + cfeat[row % 256]   (1536 x 1536, K=64)
        k_gemm<<<dim3(24, 24), 256>>>(E, 64, Wcat, 1536, QKVC, 1536, 64,
                                      (const float*)0, cfeat, 256, 1536, 0);
        k_attn<<<BMT, 256>>>(f);
        // wo = ctx @ W_o + b_o                 (1536 x 512, K=512)
        k_gemm<<<dim3(8, 24), 256>>>(ctx, 512, Wo, 512, wo, 512, 512,
                                     bo, (const float*)0, 1, 0, 0);
        k_ln<<<BMT, 256>>>(xlast, wo, ln1g, ln1b, h1);
        // ff1 = relu(h1 @ W_ff1 + b_ff1)       (1536 x 2048, K=512)
        k_gemm<<<dim3(32, 24), 256>>>(h1, 512, Wff1, 2048, ff1, 2048, 512,
                                      bff1, (const float*)0, 1, 0, 1);
        // ff2 = ff1 @ W_ff2 + b_ff2            (1536 x 512, K=2048)
        k_gemm<<<dim3(8, 24), 256>>>(ff1, 2048, Wff2, 512, ff2, 512, 2048,
                                     bff2, (const float*)0, 1, 0, 0);
        k_ln<<<BMT, 256>>>(h1, ff2, ln2g, ln2b, h2);
        // fus = h2 @ W_fus[0:512,:] + rowfus   (1536 x 448, K=512)
        k_gemm<<<dim3(7, 24), 256>>>(h2, 512, Wfus, 448, fus, 448, 512,
                                     (const float*)0, rowfus, BMT, 448, 0);
        k_finish<<<BMT, 128>>>(Wout, bout, Wemb, bemb, outp, f);
        // eKV[f] = emb_new @ W_qkv[0:32, 512:1536]  (1536 x 1024, K=32)
        k_gemm<<<dim3(16, 24), 256>>>(emb, 32, Wqkv + 512, 1536,
                                      eKV + (size_t)f * BMT * 1024, 1024, 32,
                                      (const float*)0, (const float*)0, 1, 0, 0);
    }
    (void)in_sizes; (void)n_in; (void)out_size;
}

// round 2
// speedup vs baseline: 1.6733x; 1.6733x over previous
#include <cuda_runtime.h>
#include <math.h>

#define NB    256      // batch
#define NM    6        // goals
#define INC   448
#define EMB   32
#define NHEAD 8
#define DFF   2048
#define OBS   20
#define HOR   30
#define DD    512      // model dim
#define LBUF  50
#define HD    64
#define BMT   1536     // NB*NM

// ------------------------- scratch (static device globals) -------------------------
__device__ __align__(256) float g_cfeat[NB*1536];      // feat @ W_qkv[64:512] + b_qkv
__device__ __align__(256) float g_cffus[NB*448];       // feat @ W_fus[519:967] + b_fus
__device__ __align__(256) float g_Wcat[64*1536];       // [extras rows; emb rows (q cols only)]
__device__ __align__(256) float g_eKV[(size_t)LBUF*BMT*1024]; // per-frame emb contribution to k|v
__device__ __align__(256) float g_E[BMT*64];           // [extras(32) | embPrev(32)]
__device__ __align__(256) float g_xlast[BMT*DD];
__device__ __align__(256) float g_rowfus[BMT*448];
__device__ __align__(256) float g_QKVC[BMT*1536];      // q | ck | cv
__device__ __align__(256) float g_ctx[BMT*DD];
__device__ __align__(256) float g_wo[BMT*DD];
__device__ __align__(256) float g_h1[BMT*DD];
__device__ __align__(256) float g_ff1[BMT*DFF];
__device__ __align__(256) float g_ff2[BMT*DD];
__device__ __align__(256) float g_h2[BMT*DD];
__device__ __align__(256) float g_fus[BMT*448];
__device__ __align__(256) float g_emb[BMT*EMB];        // emb of frame f-1
__device__ __align__(256) float g_last[BMT*2];

// --------------------------- TF32 helpers ----------------------------------------
__device__ __forceinline__ unsigned f2tf(float x) {
    unsigned u;
    asm("cvt.rna.tf32.f32 %0, %1;" : "=r"(u) : "f"(x));
    return u;
}

__device__ __forceinline__ void mma8(float* d, const unsigned* a, const unsigned* b) {
    asm volatile(
        "mma.sync.aligned.m16n8k8.row.col.f32.tf32.tf32.f32 "
        "{%0,%1,%2,%3}, {%4,%5,%6,%7}, {%8,%9}, {%0,%1,%2,%3};"
        : "+f"(d[0]), "+f"(d[1]), "+f"(d[2]), "+f"(d[3])
        : "r"(a[0]), "r"(a[1]), "r"(a[2]), "r"(a[3]), "r"(b[0]), "r"(b[1]));
}

// --------------- TF32 tensor-core GEMM: C = A@B (+bias)(+rowadd)(relu) ------------
// Block tile 128x64, BK=32, 256 threads (8 warps, 4x2), warp tile 32x32.
// M % 128 == 0, N % 64 == 0, K % 32 == 0, lda/ldb/ldc % 4 == 0.
__global__ void k_gemm(const float* __restrict__ A, int lda,
                       const float* __restrict__ Bm, int ldb,
                       float* __restrict__ C, int ldc,
                       int K,
                       const float* __restrict__ bias,
                       const float* __restrict__ rowadd, int ramod, int ldra,
                       int relu)
{
    __shared__ __align__(16) unsigned As[128 * 36];   // [m][k] stride 36
    __shared__ __align__(16) unsigned Bs[32 * 68];    // [k][n] stride 68
    const int row0 = blockIdx.y * 128, col0 = blockIdx.x * 64;
    const int tid  = threadIdx.x;
    const int warp = tid >> 5, lane = tid & 31;
    const int wm = warp >> 1, wn = warp & 1;
    const int l4 = lane >> 2, lm4 = lane & 3;

    float acc[2][4][4] = {};

    for (int k0 = 0; k0 < K; k0 += 32) {
        // A tile: 128 x 32 floats -> tf32
#pragma unroll
        for (int it = 0; it < 4; it++) {
            int r  = (tid >> 3) + it * 32;
            int kq = (tid & 7) * 4;
            float4 v = *(const float4*)(A + (size_t)(row0 + r) * lda + k0 + kq);
            unsigned* p = &As[r * 36 + kq];
            p[0] = f2tf(v.x); p[1] = f2tf(v.y); p[2] = f2tf(v.z); p[3] = f2tf(v.w);
        }
        // B tile: 32 x 64 floats -> tf32
#pragma unroll
        for (int it = 0; it < 2; it++) {
            int r  = (tid >> 4) + it * 16;
            int cq = (tid & 15) * 4;
            float4 v = *(const float4*)(Bm + (size_t)(k0 + r) * ldb + col0 + cq);
            unsigned* p = &Bs[r * 68 + cq];
            p[0] = f2tf(v.x); p[1] = f2tf(v.y); p[2] = f2tf(v.z); p[3] = f2tf(v.w);
        }
        __syncthreads();
#pragma unroll
        for (int ks = 0; ks < 4; ks++) {
            const int kk = ks * 8;
            unsigned a[2][4], b[4][2];
#pragma unroll
            for (int mi = 0; mi < 2; mi++) {
                int mb = wm * 32 + mi * 16 + l4;
                a[mi][0] = As[mb * 36 + kk + lm4];
                a[mi][1] = As[(mb + 8) * 36 + kk + lm4];
                a[mi][2] = As[mb * 36 + kk + lm4 + 4];
                a[mi][3] = As[(mb + 8) * 36 + kk + lm4 + 4];
            }
#pragma unroll
            for (int nj = 0; nj < 4; nj++) {
                int nb = wn * 32 + nj * 8 + l4;
                b[nj][0] = Bs[(kk + lm4) * 68 + nb];
                b[nj][1] = Bs[(kk + lm4 + 4) * 68 + nb];
            }
#pragma unroll
            for (int mi = 0; mi < 2; mi++)
#pragma unroll
                for (int nj = 0; nj < 4; nj++)
                    mma8(acc[mi][nj], a[mi], b[nj]);
        }
        __syncthreads();
    }

    // Epilogue
#pragma unroll
    for (int mi = 0; mi < 2; mi++) {
        const int rb = row0 + wm * 32 + mi * 16 + l4;
#pragma unroll
        for (int nj = 0; nj < 4; nj++) {
            const int c = col0 + wn * 32 + nj * 8 + lm4 * 2;
#pragma unroll
            for (int h = 0; h < 2; h++) {          // h=0: row rb, h=1: row rb+8
                const int r = rb + h * 8;
                float v0 = acc[mi][nj][h * 2 + 0];
                float v1 = acc[mi][nj][h * 2 + 1];
                if (bias) { v0 += bias[c]; v1 += bias[c + 1]; }
                if (rowadd) {
                    const float* ra = rowadd + (size_t)(r % ramod) * ldra + c;
                    v0 += ra[0]; v1 += ra[1];
                }
                if (relu) { v0 = fmaxf(v0, 0.f); v1 = fmaxf(v1, 0.f); }
                *(float2*)(C + (size_t)r * ldc + c) = make_float2(v0, v1);
            }
        }
    }
}

// ------------------------- one-time: build Wcat (64 x 1536) -----------------------
__global__ void k_wcat(const float* __restrict__ Wqkv)
{
    int i = blockIdx.x * blockDim.x + threadIdx.x;
    if (i >= 64 * 1536) return;
    int r = i / 1536, c = i - r * 1536;
    float v;
    if (r < 32) v = Wqkv[(32 + r) * 1536 + c];
    else        v = (c < 512) ? Wqkv[(r - 32) * 1536 + c] : 0.f;
    g_Wcat[i] = v;
}

// ------------------------- one-time: obs frames -> eKV, init emb/last -------------
__global__ void k_p1(const float* __restrict__ obs, const float* __restrict__ Wemb,
                     const float* __restrict__ bemb, const float* __restrict__ Wqkv)
{
    int bm = blockIdx.x, l = blockIdx.y, tid = threadIdx.x;
    int b = bm & 255;
    __shared__ float se[32];
    if (tid < 32) {
        float o0 = obs[(l * NB + b) * 2 + 0];
        float o1 = obs[(l * NB + b) * 2 + 1];
        se[tid] = fmaxf(o0 * Wemb[tid] + o1 * Wemb[32 + tid] + bemb[tid], 0.f);
    }
    __syncthreads();
    float* dst = g_eKV + ((size_t)l * BMT + bm) * 1024;
    for (int c = tid; c < 1024; c += 128) {
        float acc = 0.f;
#pragma unroll
        for (int e = 0; e < 32; e++) acc += se[e] * Wqkv[e * 1536 + 512 + c];
        dst[c] = acc;
    }
    if (l == OBS - 1) {
        if (tid < 32) g_emb[bm * 32 + tid] = se[tid];
        if (tid < 2)  g_last[bm * 2 + tid] = obs[((OBS - 1) * NB + b) * 2 + tid];
    }
}

// ------------------------- per-step: extras / E / xlast / rowfus ------------------
__global__ void k_prep(const float* __restrict__ loc, const float* __restrict__ feat,
                       const float* __restrict__ Wfus, int f)
{
    int bm = blockIdx.x, tid = threadIdx.x;
    int b = bm & 255, m = bm >> 8;
    float gx = loc[(b * NM + m) * 2 + 0], gy = loc[(b * NM + m) * 2 + 1];
    float lx = g_last[bm * 2 + 0], ly = g_last[bm * 2 + 1];
    float dx = gx - lx, dy = gy - ly;
    float t = (float)f;
    __shared__ float ex[32];
    if (tid < 32) {
        float v;
        if (tid < 8)       v = (tid & 1) ? gy : gx;
        else if (tid < 16) v = (tid & 1) ? ly : lx;
        else if (tid < 24) v = (tid & 1) ? dy : dx;
        else               v = t;
        ex[tid] = v;
        g_E[bm * 64 + tid] = v;
        g_E[bm * 64 + 32 + tid] = g_emb[bm * 32 + tid];
    }
    __syncthreads();
    for (int c = tid; c < 512; c += 128) {
        float v;
        if (c < 32)      v = g_emb[bm * 32 + c];
        else if (c < 64) v = ex[c - 32];
        else             v = feat[b * INC + (c - 64)];
        g_xlast[bm * 512 + c] = v;
    }
    for (int c = tid; c < 448; c += 128) {
        float v = g_cffus[b * 448 + c];
        v += lx * Wfus[(512 + 0) * 448 + c];
        v += ly * Wfus[(512 + 1) * 448 + c];
        v += gx * Wfus[(512 + 2) * 448 + c];
        v += gy * Wfus[(512 + 3) * 448 + c];
        v += dx * Wfus[(512 + 4) * 448 + c];
        v += dy * Wfus[(512 + 5) * 448 + c];
        v += t  * Wfus[(512 + 6) * 448 + c];
        g_rowfus[bm * 448 + c] = v;
    }
}

// ------------------------- per-step attention (one block per bm, warp per head) ---
__global__ void k_attn(int f)
{
    int bm = blockIdx.x;
    int tid = threadIdx.x, w = tid >> 5, lane = tid & 31;
    const float* qp = g_QKVC + (size_t)bm * 1536 + w * 64;
    float q0 = qp[lane], q1 = qp[lane + 32];
    const float* ckp = qp + 512;
    float s = q0 * ckp[lane] + q1 * ckp[lane + 32];
#pragma unroll
    for (int o = 16; o; o >>= 1) s += __shfl_xor_sync(0xffffffffu, s, o);
    const float qdot = s;
    __shared__ float sp[8][56];
    const float* kbase = g_eKV + (size_t)bm * 1024 + w * 64;
    for (int l = 0; l < f; l++) {
        const float* kp = kbase + (size_t)l * BMT * 1024;
        float d = q0 * kp[lane] + q1 * kp[lane + 32];
#pragma unroll
        for (int o = 16; o; o >>= 1) d += __shfl_xor_sync(0xffffffffu, d, o);
        if (lane == 0) sp[w][l] = (d + qdot) * 0.125f;
    }
    __syncwarp();
    float mx = -1e30f;
    if (lane < f)      mx = sp[w][lane];
    if (lane + 32 < f) mx = fmaxf(mx, sp[w][lane + 32]);
#pragma unroll
    for (int o = 16; o; o >>= 1) mx = fmaxf(mx, __shfl_xor_sync(0xffffffffu, mx, o));
    float e0 = 0.f, e1 = 0.f;
    if (lane < f)      e0 = expf(sp[w][lane] - mx);
    if (lane + 32 < f) e1 = expf(sp[w][lane + 32] - mx);
    float sum = e0 + e1;
#pragma unroll
    for (int o = 16; o; o >>= 1) sum += __shfl_xor_sync(0xffffffffu, sum, o);
    if (lane < f)      sp[w][lane] = e0;
    if (lane + 32 < f) sp[w][lane + 32] = e1;
    __syncwarp();
    float inv = 1.f / sum;
    const float* cvp = qp + 1024;
    const float* vbase = kbase + 512;
    float a0 = 0.f, a1 = 0.f;
    for (int l = 0; l < f; l++) {
        float p = sp[w][l];
        const float* vp = vbase + (size_t)l * BMT * 1024;
        a0 += p * vp[lane];
        a1 += p * vp[lane + 32];
    }
    g_ctx[(size_t)bm * 512 + w * 64 + lane]      = cvp[lane]      + a0 * inv;
    g_ctx[(size_t)bm * 512 + w * 64 + lane + 32] = cvp[lane + 32] + a1 * inv;
}

// ------------------------- layernorm over 512: out = LN(x1+x2)*g+b ----------------
__global__ void k_ln(const float* __restrict__ x1, const float* __restrict__ x2,
                     const float* __restrict__ g, const float* __restrict__ bb,
                     float* __restrict__ out)
{
    int row = blockIdx.x, tid = threadIdx.x;
    __shared__ float red[256];
    float v0 = x1[(size_t)row * 512 + tid]       + x2[(size_t)row * 512 + tid];
    float v1 = x1[(size_t)row * 512 + tid + 256] + x2[(size_t)row * 512 + tid + 256];
    red[tid] = v0 + v1;
    __syncthreads();
    for (int s = 128; s; s >>= 1) { if (tid < s) red[tid] += red[tid + s]; __syncthreads(); }
    float mu = red[0] * (1.f / 512.f);
    __syncthreads();
    float d0 = v0 - mu, d1 = v1 - mu;
    red[tid] = d0 * d0 + d1 * d1;
    __syncthreads();
    for (int s = 128; s; s >>= 1) { if (tid < s) red[tid] += red[tid + s]; __syncthreads(); }
    float rs = rsqrtf(red[0] * (1.f / 512.f) + 1e-5f);
    out[(size_t)row * 512 + tid]       = d0 * rs * g[tid] + bb[tid];
    out[(size_t)row * 512 + tid + 256] = d1 * rs * g[tid + 256] + bb[tid + 256];
}

// ------------------------- per-step epilogue: out, write, emb update --------------
__global__ void k_finish(const float* __restrict__ Wout, const float* __restrict__ bout,
                         const float* __restrict__ Wemb, const float* __restrict__ bemb,
                         float* __restrict__ dout, int f)
{
    int bm = blockIdx.x, tid = threadIdx.x;
    int b = bm & 255, m = bm >> 8;
    __shared__ float r0[128], r1[128];
    float s0 = 0.f, s1 = 0.f;
    const float* fp = g_fus + (size_t)bm * 448;
    for (int c = tid; c < 448; c += 128) {
        float v = fp[c];
        s0 += v * Wout[c * 2 + 0];
        s1 += v * Wout[c * 2 + 1];
    }
    r0[tid] = s0; r1[tid] = s1;
    __syncthreads();
    for (int s = 64; s; s >>= 1) {
        if (tid < s) { r0[tid] += r0[tid + s]; r1[tid] += r1[tid + s]; }
        __syncthreads();
    }
    float o0 = r0[0] + bout[0];
    float o1 = r1[0] + bout[1];
    if (tid < 32) {
        float e = o0 * Wemb[tid] + o1 * Wemb[32 + tid] + bemb[tid];
        g_emb[bm * 32 + tid] = fmaxf(e, 0.f);
    }
    if (tid == 0) {
        g_last[bm * 2 + 0] = o0;
        g_last[bm * 2 + 1] = o1;
        int t = f - OBS;
        dout[b * (NM * HOR * 2) + m * (HOR * 2) + t * 2 + 0] = o0;
        dout[b * (NM * HOR * 2) + m * (HOR * 2) + t * 2 + 1] = o1;
    }
}

// ----------------------------------- launch ---------------------------------------
extern "C" void kernel_launch(void* const* d_in, const int* in_sizes, int n_in,
                              void* d_out, int out_size)
{
    const float* feat = (const float*)d_in[0];
    const float* loc  = (const float*)d_in[1];
    const float* obs  = (const float*)d_in[2];
    const float* Wemb = (const float*)d_in[3];
    const float* bemb = (const float*)d_in[4];
    const float* Wqkv = (const float*)d_in[5];
    const float* bqkv = (const float*)d_in[6];
    const float* Wo   = (const float*)d_in[7];
    const float* bo   = (const float*)d_in[8];
    const float* Wff1 = (const float*)d_in[9];
    const float* bff1 = (const float*)d_in[10];
    const float* Wff2 = (const float*)d_in[11];
    const float* bff2 = (const float*)d_in[12];
    const float* ln1g = (const float*)d_in[13];
    const float* ln1b = (const float*)d_in[14];
    const float* ln2g = (const float*)d_in[15];
    const float* ln2b = (const float*)d_in[16];
    const float* Wfus = (const float*)d_in[17];
    const float* bfus = (const float*)d_in[18];
    const float* Wout = (const float*)d_in[19];
    const float* bout = (const float*)d_in[20];
    float* outp = (float*)d_out;

    float *cfeat, *cffus, *Wcat, *eKV, *E, *xlast, *rowfus, *QKVC, *ctx, *wo,
          *h1, *ff1, *ff2, *h2, *fus, *emb;
    cudaGetSymbolAddress((void**)&cfeat,  g_cfeat);
    cudaGetSymbolAddress((void**)&cffus,  g_cffus);
    cudaGetSymbolAddress((void**)&Wcat,   g_Wcat);
    cudaGetSymbolAddress((void**)&eKV,    g_eKV);
    cudaGetSymbolAddress((void**)&E,      g_E);
    cudaGetSymbolAddress((void**)&xlast,  g_xlast);
    cudaGetSymbolAddress((void**)&rowfus, g_rowfus);
    cudaGetSymbolAddress((void**)&QKVC,   g_QKVC);
    cudaGetSymbolAddress((void**)&ctx,    g_ctx);
    cudaGetSymbolAddress((void**)&wo,     g_wo);
    cudaGetSymbolAddress((void**)&h1,     g_h1);
    cudaGetSymbolAddress((void**)&ff1,    g_ff1);
    cudaGetSymbolAddress((void**)&ff2,    g_ff2);
    cudaGetSymbolAddress((void**)&h2,     g_h2);
    cudaGetSymbolAddress((void**)&fus,    g_fus);
    cudaGetSymbolAddress((void**)&emb,    g_emb);

    // one-time precompute (inside the graph; cheap + deterministic)
    k_wcat<<<(64 * 1536 + 255) / 256, 256>>>(Wqkv);
    // cfeat = feat @ W_qkv[64:512,:] + b_qkv   (256 x 1536, K=448)
    k_gemm<<<dim3(1536 / 64, NB / 128), 256>>>(feat, 448, Wqkv + 64 * 1536, 1536,
                                               cfeat, 1536, 448, bqkv, (const float*)0, 1, 0, 0);
    // cffus = feat @ W_fus[519:967,:] + b_fus  (256 x 448, K=448)
    k_gemm<<<dim3(448 / 64, NB / 128), 256>>>(feat, 448, Wfus + 519 * 448, 448,
                                              cffus, 448, 448, bfus, (const float*)0, 1, 0, 0);
    k_p1<<<dim3(BMT, OBS), 128>>>(obs, Wemb, bemb, Wqkv);

    for (int f = OBS; f < OBS + HOR; f++) {
        k_prep<<<BMT, 128>>>(loc, feat, Wfus, f);
        // QKVC = E @ Wcat + cfeat[row % 256]   (1536 x 1536, K=64)
        k_gemm<<<dim3(24, 12), 256>>>(E, 64, Wcat, 1536, QKVC, 1536, 64,
                                      (const float*)0, cfeat, 256, 1536, 0);
        k_attn<<<BMT, 256>>>(f);
        // wo = ctx @ W_o + b_o                 (1536 x 512, K=512)
        k_gemm<<<dim3(8, 12), 256>>>(ctx, 512, Wo, 512, wo, 512, 512,
                                     bo, (const float*)0, 1, 0, 0);
        k_ln<<<BMT, 256>>>(xlast, wo, ln1g, ln1b, h1);
        // ff1 = relu(h1 @ W_ff1 + b_ff1)       (1536 x 2048, K=512)
        k_gemm<<<dim3(32, 12), 256>>>(h1, 512, Wff1, 2048, ff1, 2048, 512,
                                      bff1, (const float*)0, 1, 0, 1);
        // ff2 = ff1 @ W_ff2 + b_ff2            (1536 x 512, K=2048)
        k_gemm<<<dim3(8, 12), 256>>>(ff1, 2048, Wff2, 512, ff2, 512, 2048,
                                     bff2, (const float*)0, 1, 0, 0);
        k_ln<<<BMT, 256>>>(h1, ff2, ln2g, ln2b, h2);
        // fus = h2 @ W_fus[0:512,:] + rowfus   (1536 x 448, K=512)
        k_gemm<<<dim3(7, 12), 256>>>(h2, 512, Wfus, 448, fus, 448, 512,
                                     (const float*)0, rowfus, BMT, 448, 0);
        k_finish<<<BMT, 128>>>(Wout, bout, Wemb, bemb, outp, f);
        // eKV[f] = emb_new @ W_qkv[0:32, 512:1536]  (1536 x 1024, K=32)
        k_gemm<<<dim3(16, 12), 256>>>(emb, 32, Wqkv + 512, 1536,
                                      eKV + (size_t)f * BMT * 1024, 1024, 32,
                                      (const float*)0, (const float*)0, 1, 0, 0);
    }
    (void)in_sizes; (void)n_in; (void)out_size;
}

// round 4
// speedup vs baseline: 2.0441x; 1.2216x over previous
#include <cuda_runtime.h>
#include <cuda_bf16.h>
#include <math.h>

#define NB    256      // batch
#define NM    6        // goals
#define INC   448
#define EMB   32
#define NHEAD 8
#define DFF   2048
#define OBS   20
#define HOR   30
#define DD    512      // model dim
#define LBUF  50
#define HD    64
#define BMT   1536     // NB*NM

// ------------------------- scratch (static device globals) -------------------------
__device__ __align__(256) float g_cfeat[NB*1536];      // feat @ W_qkv[64:512] + b_qkv
__device__ __align__(256) float g_cffus[NB*448];       // feat @ W_fus[519:967] + b_fus
__device__ __align__(256) float g_Wcat[64*1536];       // [extras rows; emb rows (q cols only)]
__device__ __align__(256) __nv_bfloat16 g_eKV[(size_t)LBUF*BMT*1024]; // emb contrib to k|v (bf16)
__device__ __align__(256) float g_E[BMT*64];           // [extras(32) | embPrev(32)]
__device__ __align__(256) float g_xlast[BMT*DD];
__device__ __align__(256) float g_rowfus[BMT*448];
__device__ __align__(256) float g_QKVC[BMT*1536];      // q | ck | cv
__device__ __align__(256) float g_ctx[BMT*DD];
__device__ __align__(256) float g_wo[BMT*DD];
__device__ __align__(256) float g_h1[BMT*DD];
__device__ __align__(256) float g_ff1[BMT*DFF];
__device__ __align__(256) float g_ff2[BMT*DD];
__device__ __align__(256) float g_h2[BMT*DD];
__device__ __align__(256) float g_fus[BMT*448];
__device__ __align__(256) float g_emb[BMT*EMB];        // emb of frame f-1
__device__ __align__(256) float g_last[BMT*2];

// --------------------------- TF32 helpers ----------------------------------------
__device__ __forceinline__ unsigned f2tf(float x) {
    unsigned u;
    asm("cvt.rna.tf32.f32 %0, %1;" : "=r"(u) : "f"(x));
    return u;
}

__device__ __forceinline__ void mma8(float* d, const unsigned* a, const unsigned* b) {
    asm volatile(
        "mma.sync.aligned.m16n8k8.row.col.f32.tf32.tf32.f32 "
        "{%0,%1,%2,%3}, {%4,%5,%6,%7}, {%8,%9}, {%0,%1,%2,%3};"
        : "+f"(d[0]), "+f"(d[1]), "+f"(d[2]), "+f"(d[3])
        : "r"(a[0]), "r"(a[1]), "r"(a[2]), "r"(a[3]), "r"(b[0]), "r"(b[1]));
}

// --------------- TF32 tensor-core GEMM: C = A@B (+bias)(+rowadd)(relu) ------------
// Block tile 128x64, BK=32, 256 threads (8 warps, 4x2), warp tile 32x32.
// Register-prefetch double buffering: next slab's global loads are issued
// before the MMA loop so DRAM/L2 latency overlaps compute.
// M % 128 == 0, N % 64 == 0, K % 32 == 0, lda/ldb/ldc % 4 == 0.
__global__ void k_gemm(const float* __restrict__ A, int lda,
                       const float* __restrict__ Bm, int ldb,
                       float* __restrict__ C, int ldc,
                       int K,
                       const float* __restrict__ bias,
                       const float* __restrict__ rowadd, int ramod, int ldra,
                       int relu)
{
    __shared__ __align__(16) unsigned As[128 * 36];   // [m][k] stride 36
    __shared__ __align__(16) unsigned Bs[32 * 68];    // [k][n] stride 68
    const int row0 = blockIdx.y * 128, col0 = blockIdx.x * 64;
    const int tid  = threadIdx.x;
    const int warp = tid >> 5, lane = tid & 31;
    const int wm = warp >> 1, wn = warp & 1;
    const int l4 = lane >> 2, lm4 = lane & 3;

    const int ar = tid >> 3, akq = (tid & 7) * 4;     // A fill coords
    const int br = tid >> 4, bcq = (tid & 15) * 4;    // B fill coords

    float acc[2][4][4] = {};
    float4 pa[4], pb[2];

    // prologue: load slab 0
#pragma unroll
    for (int it = 0; it < 4; it++)
        pa[it] = *(const float4*)(A + (size_t)(row0 + ar + it * 32) * lda + akq);
#pragma unroll
    for (int it = 0; it < 2; it++)
        pb[it] = *(const float4*)(Bm + (size_t)(br + it * 16) * ldb + col0 + bcq);

    for (int k0 = 0; k0 < K; k0 += 32) {
        // store current slab (cvt to tf32)
#pragma unroll
        for (int it = 0; it < 4; it++) {
            unsigned* p = &As[(ar + it * 32) * 36 + akq];
            p[0] = f2tf(pa[it].x); p[1] = f2tf(pa[it].y);
            p[2] = f2tf(pa[it].z); p[3] = f2tf(pa[it].w);
        }
#pragma unroll
        for (int it = 0; it < 2; it++) {
            unsigned* p = &Bs[(br + it * 16) * 68 + bcq];
            p[0] = f2tf(pb[it].x); p[1] = f2tf(pb[it].y);
            p[2] = f2tf(pb[it].z); p[3] = f2tf(pb[it].w);
        }
        __syncthreads();

        // prefetch next slab (loads in flight during MMA)
        if (k0 + 32 < K) {
#pragma unroll
            for (int it = 0; it < 4; it++)
                pa[it] = *(const float4*)(A + (size_t)(row0 + ar + it * 32) * lda + k0 + 32 + akq);
#pragma unroll
            for (int it = 0; it < 2; it++)
                pb[it] = *(const float4*)(Bm + (size_t)(k0 + 32 + br + it * 16) * ldb + col0 + bcq);
        }

#pragma unroll
        for (int ks = 0; ks < 4; ks++) {
            const int kk = ks * 8;
            unsigned a[2][4], b[4][2];
#pragma unroll
            for (int mi = 0; mi < 2; mi++) {
                int mb = wm * 32 + mi * 16 + l4;
                a[mi][0] = As[mb * 36 + kk + lm4];
                a[mi][1] = As[(mb + 8) * 36 + kk + lm4];
                a[mi][2] = As[mb * 36 + kk + lm4 + 4];
                a[mi][3] = As[(mb + 8) * 36 + kk + lm4 + 4];
            }
#pragma unroll
            for (int nj = 0; nj < 4; nj++) {
                int nb = wn * 32 + nj * 8 + l4;
                b[nj][0] = Bs[(kk + lm4) * 68 + nb];
                b[nj][1] = Bs[(kk + lm4 + 4) * 68 + nb];
            }
#pragma unroll
            for (int mi = 0; mi < 2; mi++)
#pragma unroll
                for (int nj = 0; nj < 4; nj++)
                    mma8(acc[mi][nj], a[mi], b[nj]);
        }
        __syncthreads();
    }

    // Epilogue
#pragma unroll
    for (int mi = 0; mi < 2; mi++) {
        const int rb = row0 + wm * 32 + mi * 16 + l4;
#pragma unroll
        for (int nj = 0; nj < 4; nj++) {
            const int c = col0 + wn * 32 + nj * 8 + lm4 * 2;
#pragma unroll
            for (int h = 0; h < 2; h++) {          // h=0: row rb, h=1: row rb+8
                const int r = rb + h * 8;
                float v0 = acc[mi][nj][h * 2 + 0];
                float v1 = acc[mi][nj][h * 2 + 1];
                if (bias) { v0 += bias[c]; v1 += bias[c + 1]; }
                if (rowadd) {
                    const float* ra = rowadd + (size_t)(r % ramod) * ldra + c;
                    v0 += ra[0]; v1 += ra[1];
                }
                if (relu) { v0 = fmaxf(v0, 0.f); v1 = fmaxf(v1, 0.f); }
                *(float2*)(C + (size_t)r * ldc + c) = make_float2(v0, v1);
            }
        }
    }
}

// ------------------------- one-time: build Wcat (64 x 1536) -----------------------
__global__ void k_wcat(const float* __restrict__ Wqkv)
{
    int i = blockIdx.x * blockDim.x + threadIdx.x;
    if (i >= 64 * 1536) return;
    int r = i / 1536, c = i - r * 1536;
    float v;
    if (r < 32) v = Wqkv[(32 + r) * 1536 + c];
    else        v = (c < 512) ? Wqkv[(r - 32) * 1536 + c] : 0.f;
    g_Wcat[i] = v;
}

// ------------------------- one-time: obs frames -> eKV, init emb/last -------------
__global__ void k_p1(const float* __restrict__ obs, const float* __restrict__ Wemb,
                     const float* __restrict__ bemb, const float* __restrict__ Wqkv)
{
    int bm = blockIdx.x, l = blockIdx.y, tid = threadIdx.x;
    int b = bm & 255;
    __shared__ float se[32];
    if (tid < 32) {
        float o0 = obs[(l * NB + b) * 2 + 0];
        float o1 = obs[(l * NB + b) * 2 + 1];
        se[tid] = fmaxf(o0 * Wemb[tid] + o1 * Wemb[32 + tid] + bemb[tid], 0.f);
    }
    __syncthreads();
    __nv_bfloat16* dst = g_eKV + ((size_t)l * BMT + bm) * 1024;
    for (int c = tid; c < 1024; c += 128) {
        float acc = 0.f;
#pragma unroll
        for (int e = 0; e < 32; e++) acc += se[e] * Wqkv[e * 1536 + 512 + c];
        dst[c] = __float2bfloat16(acc);
    }
    if (l == OBS - 1) {
        if (tid < 32) g_emb[bm * 32 + tid] = se[tid];
        if (tid < 2)  g_last[bm * 2 + tid] = obs[((OBS - 1) * NB + b) * 2 + tid];
    }
}

// ------------------------- initial prep (f = OBS only) ----------------------------
__global__ void k_prep(const float* __restrict__ loc, const float* __restrict__ feat,
                       const float* __restrict__ Wfus, int f)
{
    int bm = blockIdx.x, tid = threadIdx.x;
    int b = bm & 255, m = bm >> 8;
    float gx = loc[(b * NM + m) * 2 + 0], gy = loc[(b * NM + m) * 2 + 1];
    float lx = g_last[bm * 2 + 0], ly = g_last[bm * 2 + 1];
    float dx = gx - lx, dy = gy - ly;
    float t = (float)f;
    __shared__ float ex[32];
    if (tid < 32) {
        float v;
        if (tid < 8)       v = (tid & 1) ? gy : gx;
        else if (tid < 16) v = (tid & 1) ? ly : lx;
        else if (tid < 24) v = (tid & 1) ? dy : dx;
        else               v = t;
        ex[tid] = v;
        g_E[bm * 64 + tid] = v;
        g_E[bm * 64 + 32 + tid] = g_emb[bm * 32 + tid];
    }
    __syncthreads();
    for (int c = tid; c < 512; c += 128) {
        float v;
        if (c < 32)      v = g_emb[bm * 32 + c];
        else if (c < 64) v = ex[c - 32];
        else             v = feat[b * INC + (c - 64)];
        g_xlast[bm * 512 + c] = v;
    }
    for (int c = tid; c < 448; c += 128) {
        float v = g_cffus[b * 448 + c];
        v += lx * Wfus[(512 + 0) * 448 + c];
        v += ly * Wfus[(512 + 1) * 448 + c];
        v += gx * Wfus[(512 + 2) * 448 + c];
        v += gy * Wfus[(512 + 3) * 448 + c];
        v += dx * Wfus[(512 + 4) * 448 + c];
        v += dy * Wfus[(512 + 5) * 448 + c];
        v += t  * Wfus[(512 + 6) * 448 + c];
        g_rowfus[bm * 448 + c] = v;
    }
}

// ------------------------- per-step attention (one block per bm, warp per head) ---
__global__ void k_attn(int f)
{
    int bm = blockIdx.x;
    int tid = threadIdx.x, w = tid >> 5, lane = tid & 31;
    const float* qp = g_QKVC + (size_t)bm * 1536 + w * 64;
    float q0 = qp[2 * lane], q1 = qp[2 * lane + 1];
    const float* ckp = qp + 512;
    float s = q0 * ckp[2 * lane] + q1 * ckp[2 * lane + 1];
#pragma unroll
    for (int o = 16; o; o >>= 1) s += __shfl_xor_sync(0xffffffffu, s, o);
    const float qdot = s;
    __shared__ float sp[8][56];
    const __nv_bfloat16* kbase = g_eKV + (size_t)bm * 1024 + w * 64;
    for (int l = 0; l < f; l++) {
        __nv_bfloat162 kv = *(const __nv_bfloat162*)(kbase + (size_t)l * BMT * 1024 + 2 * lane);
        float2 kf = __bfloat1622float2(kv);
        float d = q0 * kf.x + q1 * kf.y;
#pragma unroll
        for (int o = 16; o; o >>= 1) d += __shfl_xor_sync(0xffffffffu, d, o);
        if (lane == 0) sp[w][l] = (d + qdot) * 0.125f;
    }
    __syncwarp();
    float mx = -1e30f;
    if (lane < f)      mx = sp[w][lane];
    if (lane + 32 < f) mx = fmaxf(mx, sp[w][lane + 32]);
#pragma unroll
    for (int o = 16; o; o >>= 1) mx = fmaxf(mx, __shfl_xor_sync(0xffffffffu, mx, o));
    float e0 = 0.f, e1 = 0.f;
    if (lane < f)      e0 = expf(sp[w][lane] - mx);
    if (lane + 32 < f) e1 = expf(sp[w][lane + 32] - mx);
    float sum = e0 + e1;
#pragma unroll
    for (int o = 16; o; o >>= 1) sum += __shfl_xor_sync(0xffffffffu, sum, o);
    if (lane < f)      sp[w][lane] = e0;
    if (lane + 32 < f) sp[w][lane + 32] = e1;
    __syncwarp();
    float inv = 1.f / sum;
    const float* cvp = qp + 1024;
    const __nv_bfloat16* vbase = kbase + 512;
    float a0 = 0.f, a1 = 0.f;
    for (int l = 0; l < f; l++) {
        float p = sp[w][l];
        __nv_bfloat162 vv = *(const __nv_bfloat162*)(vbase + (size_t)l * BMT * 1024 + 2 * lane);
        float2 vf = __bfloat1622float2(vv);
        a0 += p * vf.x;
        a1 += p * vf.y;
    }
    float* op = g_ctx + (size_t)bm * 512 + w * 64 + 2 * lane;
    *(float2*)op = make_float2(cvp[2 * lane] + a0 * inv, cvp[2 * lane + 1] + a1 * inv);
}

// ------------------------- layernorm over 512: out = LN(x1+x2)*g+b ----------------
__global__ void k_ln(const float* __restrict__ x1, const float* __restrict__ x2,
                     const float* __restrict__ g, const float* __restrict__ bb,
                     float* __restrict__ out)
{
    int row = blockIdx.x, tid = threadIdx.x;
    __shared__ float red[256];
    float v0 = x1[(size_t)row * 512 + tid]       + x2[(size_t)row * 512 + tid];
    float v1 = x1[(size_t)row * 512 + tid + 256] + x2[(size_t)row * 512 + tid + 256];
    red[tid] = v0 + v1;
    __syncthreads();
    for (int s = 128; s; s >>= 1) { if (tid < s) red[tid] += red[tid + s]; __syncthreads(); }
    float mu = red[0] * (1.f / 512.f);
    __syncthreads();
    float d0 = v0 - mu, d1 = v1 - mu;
    red[tid] = d0 * d0 + d1 * d1;
    __syncthreads();
    for (int s = 128; s; s >>= 1) { if (tid < s) red[tid] += red[tid + s]; __syncthreads(); }
    float rs = rsqrtf(red[0] * (1.f / 512.f) + 1e-5f);
    out[(size_t)row * 512 + tid]       = d0 * rs * g[tid] + bb[tid];
    out[(size_t)row * 512 + tid + 256] = d1 * rs * g[tid + 256] + bb[tid + 256];
}

// ---- fused per-step epilogue: out + emb + eKV[f] + prep for step f+1 ------------
__global__ void k_step(const float* __restrict__ Wout, const float* __restrict__ bout,
                       const float* __restrict__ Wemb, const float* __restrict__ bemb,
                       const float* __restrict__ Wqkv,
                       const float* __restrict__ loc, const float* __restrict__ feat,
                       const float* __restrict__ Wfus,
                       float* __restrict__ dout, int f)
{
    int bm = blockIdx.x, tid = threadIdx.x;
    int b = bm & 255, m = bm >> 8;
    __shared__ float r0[128], r1[128];
    __shared__ float se[32], ex[32];

    // out = fus @ W_out + b_out
    float s0 = 0.f, s1 = 0.f;
    const float* fp = g_fus + (size_t)bm * 448;
    for (int c = tid; c < 448; c += 128) {
        float v = fp[c];
        s0 += v * Wout[c * 2 + 0];
        s1 += v * Wout[c * 2 + 1];
    }
    r0[tid] = s0; r1[tid] = s1;
    __syncthreads();
    for (int s = 64; s; s >>= 1) {
        if (tid < s) { r0[tid] += r0[tid + s]; r1[tid] += r1[tid + s]; }
        __syncthreads();
    }
    float o0 = r0[0] + bout[0];
    float o1 = r1[0] + bout[1];

    // emb_new = relu(out @ W_emb + b_emb)
    if (tid < 32) {
        float e = fmaxf(o0 * Wemb[tid] + o1 * Wemb[32 + tid] + bemb[tid], 0.f);
        se[tid] = e;
        g_emb[bm * 32 + tid] = e;
    }
    if (tid == 0) {
        g_last[bm * 2 + 0] = o0;
        g_last[bm * 2 + 1] = o1;
        int t = f - OBS;
        dout[b * (NM * HOR * 2) + m * (HOR * 2) + t * 2 + 0] = o0;
        dout[b * (NM * HOR * 2) + m * (HOR * 2) + t * 2 + 1] = o1;
    }
    __syncthreads();

    // eKV[f] = emb_new @ W_qkv[0:32, 512:1536]   (bf16, coalesced W reads, L2-resident)
    __nv_bfloat16* dst = g_eKV + ((size_t)f * BMT + bm) * 1024;
    for (int c = tid; c < 1024; c += 128) {
        float acc = 0.f;
#pragma unroll
        for (int e = 0; e < 32; e++) acc += se[e] * Wqkv[e * 1536 + 512 + c];
        dst[c] = __float2bfloat16(acc);
    }

    // prep for next step
    int fn = f + 1;
    if (fn < OBS + HOR) {
        float gx = loc[(b * NM + m) * 2 + 0], gy = loc[(b * NM + m) * 2 + 1];
        float dx = gx - o0, dy = gy - o1;
        float t = (float)fn;
        if (tid < 32) {
            float v;
            if (tid < 8)       v = (tid & 1) ? gy : gx;
            else if (tid < 16) v = (tid & 1) ? o1 : o0;
            else if (tid < 24) v = (tid & 1) ? dy : dx;
            else               v = t;
            ex[tid] = v;
            g_E[bm * 64 + tid] = v;
            g_E[bm * 64 + 32 + tid] = se[tid];
        }
        __syncthreads();
        for (int c = tid; c < 512; c += 128) {
            float v;
            if (c < 32)      v = se[c];
            else if (c < 64) v = ex[c - 32];
            else             v = feat[b * INC + (c - 64)];
            g_xlast[bm * 512 + c] = v;
        }
        for (int c = tid; c < 448; c += 128) {
            float v = g_cffus[b * 448 + c];
            v += o0 * Wfus[(512 + 0) * 448 + c];
            v += o1 * Wfus[(512 + 1) * 448 + c];
            v += gx * Wfus[(512 + 2) * 448 + c];
            v += gy * Wfus[(512 + 3) * 448 + c];
            v += dx * Wfus[(512 + 4) * 448 + c];
            v += dy * Wfus[(512 + 5) * 448 + c];
            v += t  * Wfus[(512 + 6) * 448 + c];
            g_rowfus[bm * 448 + c] = v;
        }
    }
}

// ----------------------------------- launch ---------------------------------------
extern "C" void kernel_launch(void* const* d_in, const int* in_sizes, int n_in,
                              void* d_out, int out_size)
{
    const float* feat = (const float*)d_in[0];
    const float* loc  = (const float*)d_in[1];
    const float* obs  = (const float*)d_in[2];
    const float* Wemb = (const float*)d_in[3];
    const float* bemb = (const float*)d_in[4];
    const float* Wqkv = (const float*)d_in[5];
    const float* bqkv = (const float*)d_in[6];
    const float* Wo   = (const float*)d_in[7];
    const float* bo   = (const float*)d_in[8];
    const float* Wff1 = (const float*)d_in[9];
    const float* bff1 = (const float*)d_in[10];
    const float* Wff2 = (const float*)d_in[11];
    const float* bff2 = (const float*)d_in[12];
    const float* ln1g = (const float*)d_in[13];
    const float* ln1b = (const float*)d_in[14];
    const float* ln2g = (const float*)d_in[15];
    const float* ln2b = (const float*)d_in[16];
    const float* Wfus = (const float*)d_in[17];
    const float* bfus = (const float*)d_in[18];
    const float* Wout = (const float*)d_in[19];
    const float* bout = (const float*)d_in[20];
    float* outp = (float*)d_out;

    float *cfeat, *cffus, *Wcat, *E, *xlast, *rowfus, *QKVC, *ctx, *wo,
          *h1, *ff1, *ff2, *h2, *fus;
    cudaGetSymbolAddress((void**)&cfeat,  g_cfeat);
    cudaGetSymbolAddress((void**)&cffus,  g_cffus);
    cudaGetSymbolAddress((void**)&Wcat,   g_Wcat);
    cudaGetSymbolAddress((void**)&E,      g_E);
    cudaGetSymbolAddress((void**)&xlast,  g_xlast);
    cudaGetSymbolAddress((void**)&rowfus, g_rowfus);
    cudaGetSymbolAddress((void**)&QKVC,   g_QKVC);
    cudaGetSymbolAddress((void**)&ctx,    g_ctx);
    cudaGetSymbolAddress((void**)&wo,     g_wo);
    cudaGetSymbolAddress((void**)&h1,     g_h1);
    cudaGetSymbolAddress((void**)&ff1,    g_ff1);
    cudaGetSymbolAddress((void**)&ff2,    g_ff2);
    cudaGetSymbolAddress((void**)&h2,     g_h2);
    cudaGetSymbolAddress((void**)&fus,    g_fus);

    // one-time precompute (inside the graph; cheap + deterministic)
    k_wcat<<<(64 * 1536 + 255) / 256, 256>>>(Wqkv);
    // cfeat = feat @ W_qkv[64:512,:] + b_qkv   (256 x 1536, K=448)
    k_gemm<<<dim3(1536 / 64, NB / 128), 256>>>(feat, 448, Wqkv + 64 * 1536, 1536,
                                               cfeat, 1536, 448, bqkv, (const float*)0, 1, 0, 0);
    // cffus = feat @ W_fus[519:967,:] + b_fus  (256 x 448, K=448)
    k_gemm<<<dim3(448 / 64, NB / 128), 256>>>(feat, 448, Wfus + 519 * 448, 448,
                                              cffus, 448, 448, bfus, (const float*)0, 1, 0, 0);
    k_p1<<<dim3(BMT, OBS), 128>>>(obs, Wemb, bemb, Wqkv);
    k_prep<<<BMT, 128>>>(loc, feat, Wfus, OBS);

    for (int f = OBS; f < OBS + HOR; f++) {
        // QKVC = E @ Wcat + cfeat[row % 256]   (1536 x 1536, K=64)
        k_gemm<<<dim3(24, 12), 256>>>(E, 64, Wcat, 1536, QKVC, 1536, 64,
                                      (const float*)0, cfeat, 256, 1536, 0);
        k_attn<<<BMT, 256>>>(f);
        // wo = ctx @ W_o + b_o                 (1536 x 512, K=512)
        k_gemm<<<dim3(8, 12), 256>>>(ctx, 512, Wo, 512, wo, 512, 512,
                                     bo, (const float*)0, 1, 0, 0);
        k_ln<<<BMT, 256>>>(xlast, wo, ln1g, ln1b, h1);
        // ff1 = relu(h1 @ W_ff1 + b_ff1)       (1536 x 2048, K=512)
        k_gemm<<<dim3(32, 12), 256>>>(h1, 512, Wff1, 2048, ff1, 2048, 512,
                                      bff1, (const float*)0, 1, 0, 1);
        // ff2 = ff1 @ W_ff2 + b_ff2            (1536 x 512, K=2048)
        k_gemm<<<dim3(8, 12), 256>>>(ff1, 2048, Wff2, 512, ff2, 512, 2048,
                                     bff2, (const float*)0, 1, 0, 0);
        k_ln<<<BMT, 256>>>(h1, ff2, ln2g, ln2b, h2);
        // fus = h2 @ W_fus[0:512,:] + rowfus   (1536 x 448, K=512)
        k_gemm<<<dim3(7, 12), 256>>>(h2, 512, Wfus, 448, fus, 448, 512,
                                     (const float*)0, rowfus, BMT, 448, 0);
        // fused: out + emb + eKV[f] + prep(f+1)
        k_step<<<BMT, 128>>>(Wout, bout, Wemb, bemb, Wqkv, loc, feat, Wfus, outp, f);
    }
    (void)in_sizes; (void)n_in; (void)out_size;
}

// round 5
// speedup vs baseline: 2.4842x; 1.2153x over previous
#include <cuda_runtime.h>
#include <cuda_bf16.h>
#include <math.h>

#define NB    256      // batch
#define NM    6        // goals
#define INC   448
#define EMB   32
#define NHEAD 8
#define DFF   2048
#define OBS   20
#define HOR   30
#define DD    512      // model dim
#define LBUF  50
#define HD    64
#define BMT   1536     // NB*NM

// ------------------------- scratch (static device globals) -------------------------
__device__ __align__(256) float g_cfeat[NB*1536];      // feat @ W_qkv[64:512] + b_qkv
__device__ __align__(256) float g_cffus[NB*448];       // feat @ W_fus[519:967] + b_fus
__device__ __align__(256) float g_Wcat[64*1536];       // [extras rows; emb rows (q cols only)]
__device__ __align__(256) float g_eobs[OBS*NB*32];     // relu(obs @ W_emb + b) per (l,b)
__device__ __align__(256) __nv_bfloat16 g_eKVo[(size_t)OBS*NB*1024];   // obs eKV, per-b (dedup x6)
__device__ __align__(256) __nv_bfloat16 g_eKV[(size_t)HOR*BMT*1024];   // rollout eKV, per-bm
__device__ __align__(256) float g_E[BMT*64];           // [extras(32) | embPrev(32)]
__device__ __align__(256) float g_xlast[BMT*DD];
__device__ __align__(256) float g_rowfus[BMT*448];
__device__ __align__(256) float g_QKVC[BMT*1536];      // q | ck | cv
__device__ __align__(256) float g_ctx[BMT*DD];
__device__ __align__(256) float g_wo[BMT*DD];
__device__ __align__(256) float g_wob[BMT*DD];
__device__ __align__(256) float g_h1[BMT*DD];
__device__ __align__(256) float g_ff1[BMT*DFF];
__device__ __align__(256) float g_ff2[BMT*DD];
__device__ __align__(256) float g_ff2b[BMT*DD];
__device__ __align__(256) float g_h2[BMT*DD];
__device__ __align__(256) float g_fus[BMT*448];
__device__ __align__(256) float g_fusb[BMT*448];
__device__ __align__(256) float g_emb[BMT*EMB];        // emb of frame f-1
__device__ __align__(256) float g_last[BMT*2];

// --------------------------- TF32 helpers ----------------------------------------
__device__ __forceinline__ unsigned f2tf(float x) {
    unsigned u;
    asm("cvt.rna.tf32.f32 %0, %1;" : "=r"(u) : "f"(x));
    return u;
}

__device__ __forceinline__ void mma8(float* d, const unsigned* a, const unsigned* b) {
    asm volatile(
        "mma.sync.aligned.m16n8k8.row.col.f32.tf32.tf32.f32 "
        "{%0,%1,%2,%3}, {%4,%5,%6,%7}, {%8,%9}, {%0,%1,%2,%3};"
        : "+f"(d[0]), "+f"(d[1]), "+f"(d[2]), "+f"(d[3])
        : "r"(a[0]), "r"(a[1]), "r"(a[2]), "r"(a[3]), "r"(b[0]), "r"(b[1]));
}

// --------------- TF32 tensor-core GEMM: C = A@B (+bias)(+rowadd)(relu) ------------
// Block tile 128x64, BK=32, 256 threads (8 warps, 4x2), warp tile 32x32.
// Register-prefetch double buffering. Optional split-K via gridDim.z==2:
// z=1 computes the upper K half into Cv2 with no bias/rowadd (caller sums).
// Optional bf16 output (obf16). M%128==0, N%64==0, K%32==0, lds%4==0.
__global__ void k_gemm(const float* __restrict__ A, int lda,
                       const float* __restrict__ Bm, int ldb,
                       void* __restrict__ Cv, int ldc,
                       int K,
                       const float* __restrict__ bias,
                       const float* __restrict__ rowadd, int ramod, int ldra,
                       int relu, int obf16, void* __restrict__ Cv2)
{
    if (blockIdx.z) {           // split-K: upper half
        A  += K;
        Bm += (size_t)K * ldb;
        Cv  = Cv2;
        bias = 0; rowadd = 0;
    }
    __shared__ __align__(16) unsigned As[128 * 36];   // [m][k] stride 36
    __shared__ __align__(16) unsigned Bs[32 * 68];    // [k][n] stride 68
    const int row0 = blockIdx.y * 128, col0 = blockIdx.x * 64;
    const int tid  = threadIdx.x;
    const int warp = tid >> 5, lane = tid & 31;
    const int wm = warp >> 1, wn = warp & 1;
    const int l4 = lane >> 2, lm4 = lane & 3;

    const int ar = tid >> 3, akq = (tid & 7) * 4;     // A fill coords
    const int br = tid >> 4, bcq = (tid & 15) * 4;    // B fill coords

    float acc[2][4][4] = {};
    float4 pa[4], pb[2];

    // prologue: load slab 0
#pragma unroll
    for (int it = 0; it < 4; it++)
        pa[it] = *(const float4*)(A + (size_t)(row0 + ar + it * 32) * lda + akq);
#pragma unroll
    for (int it = 0; it < 2; it++)
        pb[it] = *(const float4*)(Bm + (size_t)(br + it * 16) * ldb + col0 + bcq);

    for (int k0 = 0; k0 < K; k0 += 32) {
        // store current slab (cvt to tf32)
#pragma unroll
        for (int it = 0; it < 4; it++) {
            unsigned* p = &As[(ar + it * 32) * 36 + akq];
            p[0] = f2tf(pa[it].x); p[1] = f2tf(pa[it].y);
            p[2] = f2tf(pa[it].z); p[3] = f2tf(pa[it].w);
        }
#pragma unroll
        for (int it = 0; it < 2; it++) {
            unsigned* p = &Bs[(br + it * 16) * 68 + bcq];
            p[0] = f2tf(pb[it].x); p[1] = f2tf(pb[it].y);
            p[2] = f2tf(pb[it].z); p[3] = f2tf(pb[it].w);
        }
        __syncthreads();

        // prefetch next slab (loads in flight during MMA)
        if (k0 + 32 < K) {
#pragma unroll
            for (int it = 0; it < 4; it++)
                pa[it] = *(const float4*)(A + (size_t)(row0 + ar + it * 32) * lda + k0 + 32 + akq);
#pragma unroll
            for (int it = 0; it < 2; it++)
                pb[it] = *(const float4*)(Bm + (size_t)(k0 + 32 + br + it * 16) * ldb + col0 + bcq);
        }

#pragma unroll
        for (int ks = 0; ks < 4; ks++) {
            const int kk = ks * 8;
            unsigned a[2][4], b[4][2];
#pragma unroll
            for (int mi = 0; mi < 2; mi++) {
                int mb = wm * 32 + mi * 16 + l4;
                a[mi][0] = As[mb * 36 + kk + lm4];
                a[mi][1] = As[(mb + 8) * 36 + kk + lm4];
                a[mi][2] = As[mb * 36 + kk + lm4 + 4];
                a[mi][3] = As[(mb + 8) * 36 + kk + lm4 + 4];
            }
#pragma unroll
            for (int nj = 0; nj < 4; nj++) {
                int nb = wn * 32 + nj * 8 + l4;
                b[nj][0] = Bs[(kk + lm4) * 68 + nb];
                b[nj][1] = Bs[(kk + lm4 + 4) * 68 + nb];
            }
#pragma unroll
            for (int mi = 0; mi < 2; mi++)
#pragma unroll
                for (int nj = 0; nj < 4; nj++)
                    mma8(acc[mi][nj], a[mi], b[nj]);
        }
        __syncthreads();
    }

    // Epilogue
#pragma unroll
    for (int mi = 0; mi < 2; mi++) {
        const int rb = row0 + wm * 32 + mi * 16 + l4;
#pragma unroll
        for (int nj = 0; nj < 4; nj++) {
            const int c = col0 + wn * 32 + nj * 8 + lm4 * 2;
#pragma unroll
            for (int h = 0; h < 2; h++) {          // h=0: row rb, h=1: row rb+8
                const int r = rb + h * 8;
                float v0 = acc[mi][nj][h * 2 + 0];
                float v1 = acc[mi][nj][h * 2 + 1];
                if (bias) { v0 += bias[c]; v1 += bias[c + 1]; }
                if (rowadd) {
                    const float* ra = rowadd + (size_t)(r % ramod) * ldra + c;
                    v0 += ra[0]; v1 += ra[1];
                }
                if (relu) { v0 = fmaxf(v0, 0.f); v1 = fmaxf(v1, 0.f); }
                if (obf16) {
                    *(__nv_bfloat162*)((__nv_bfloat16*)Cv + (size_t)r * ldc + c) =
                        __floats2bfloat162_rn(v0, v1);
                } else {
                    *(float2*)((float*)Cv + (size_t)r * ldc + c) = make_float2(v0, v1);
                }
            }
        }
    }
}

// ------------------------- one-time: build Wcat (64 x 1536) -----------------------
__global__ void k_wcat(const float* __restrict__ Wqkv)
{
    int i = blockIdx.x * blockDim.x + threadIdx.x;
    if (i >= 64 * 1536) return;
    int r = i / 1536, c = i - r * 1536;
    float v;
    if (r < 32) v = Wqkv[(32 + r) * 1536 + c];
    else        v = (c < 512) ? Wqkv[(r - 32) * 1536 + c] : 0.f;
    g_Wcat[i] = v;
}

// ------------------------- one-time: emb of obs frames (per l,b) ------------------
__global__ void k_eobs(const float* __restrict__ obs, const float* __restrict__ Wemb,
                       const float* __restrict__ bemb)
{
    int r = blockIdx.x, t = threadIdx.x;   // r = l*NB + b, t < 32
    float o0 = obs[r * 2 + 0], o1 = obs[r * 2 + 1];
    g_eobs[r * 32 + t] = fmaxf(o0 * Wemb[t] + o1 * Wemb[32 + t] + bemb[t], 0.f);
}

// ------------------------- one-time: init emb/last from obs frame 19 --------------
__global__ void k_init(const float* __restrict__ obs)
{
    int bm = blockIdx.x, t = threadIdx.x;
    int b = bm & 255;
    g_emb[bm * 32 + t] = g_eobs[((OBS - 1) * NB + b) * 32 + t];
    if (t < 2) g_last[bm * 2 + t] = obs[((OBS - 1) * NB + b) * 2 + t];
}

// ------------------------- initial prep (f = OBS only) ----------------------------
__global__ void k_prep(const float* __restrict__ loc, const float* __restrict__ feat,
                       const float* __restrict__ Wfus, int f)
{
    int bm = blockIdx.x, tid = threadIdx.x;
    int b = bm & 255, m = bm >> 8;
    float gx = loc[(b * NM + m) * 2 + 0], gy = loc[(b * NM + m) * 2 + 1];
    float lx = g_last[bm * 2 + 0], ly = g_last[bm * 2 + 1];
    float dx = gx - lx, dy = gy - ly;
    float t = (float)f;
    __shared__ float ex[32];
    if (tid < 32) {
        float v;
        if (tid < 8)       v = (tid & 1) ? gy : gx;
        else if (tid < 16) v = (tid & 1) ? ly : lx;
        else if (tid < 24) v = (tid & 1) ? dy : dx;
        else               v = t;
        ex[tid] = v;
        g_E[bm * 64 + tid] = v;
        g_E[bm * 64 + 32 + tid] = g_emb[bm * 32 + tid];
    }
    __syncthreads();
    for (int c = tid; c < 512; c += 128) {
        float v;
        if (c < 32)      v = g_emb[bm * 32 + c];
        else if (c < 64) v = ex[c - 32];
        else             v = feat[b * INC + (c - 64)];
        g_xlast[bm * 512 + c] = v;
    }
    for (int c = tid; c < 448; c += 128) {
        float v = g_cffus[b * 448 + c];
        v += lx * Wfus[(512 + 0) * 448 + c];
        v += ly * Wfus[(512 + 1) * 448 + c];
        v += gx * Wfus[(512 + 2) * 448 + c];
        v += gy * Wfus[(512 + 3) * 448 + c];
        v += dx * Wfus[(512 + 4) * 448 + c];
        v += dy * Wfus[(512 + 5) * 448 + c];
        v += t  * Wfus[(512 + 6) * 448 + c];
        g_rowfus[bm * 448 + c] = v;
    }
}

// ------------------------- per-step attention (one block per bm, warp per head) ---
// obs frames (l<OBS) read per-b deduped cache g_eKVo; rollout frames read g_eKV.
__global__ void k_attn(int f)
{
    int bm = blockIdx.x;
    int tid = threadIdx.x, w = tid >> 5, lane = tid & 31;
    int b = bm & 255;
    const float* qp = g_QKVC + (size_t)bm * 1536 + w * 64;
    float q0 = qp[2 * lane], q1 = qp[2 * lane + 1];
    const float* ckp = qp + 512;
    float s = q0 * ckp[2 * lane] + q1 * ckp[2 * lane + 1];
#pragma unroll
    for (int o = 16; o; o >>= 1) s += __shfl_xor_sync(0xffffffffu, s, o);
    const float qdot = s;
    __shared__ float sp[8][56];
    const int off = w * 64 + 2 * lane;
    const __nv_bfloat16* ob = g_eKVo + (size_t)b * 1024 + off;
    const __nv_bfloat16* rb = g_eKV + (size_t)bm * 1024 + off;
    const int fr = f - OBS;
    for (int l = 0; l < OBS; l++) {
        float2 kf = __bfloat1622float2(*(const __nv_bfloat162*)(ob + (size_t)l * NB * 1024));
        float d = q0 * kf.x + q1 * kf.y;
#pragma unroll
        for (int o = 16; o; o >>= 1) d += __shfl_xor_sync(0xffffffffu, d, o);
        if (lane == 0) sp[w][l] = (d + qdot) * 0.125f;
    }
    for (int l = 0; l < fr; l++) {
        float2 kf = __bfloat1622float2(*(const __nv_bfloat162*)(rb + (size_t)l * BMT * 1024));
        float d = q0 * kf.x + q1 * kf.y;
#pragma unroll
        for (int o = 16; o; o >>= 1) d += __shfl_xor_sync(0xffffffffu, d, o);
        if (lane == 0) sp[w][OBS + l] = (d + qdot) * 0.125f;
    }
    __syncwarp();
    float mx = -1e30f;
    if (lane < f)      mx = sp[w][lane];
    if (lane + 32 < f) mx = fmaxf(mx, sp[w][lane + 32]);
#pragma unroll
    for (int o = 16; o; o >>= 1) mx = fmaxf(mx, __shfl_xor_sync(0xffffffffu, mx, o));
    float e0 = 0.f, e1 = 0.f;
    if (lane < f)      e0 = expf(sp[w][lane] - mx);
    if (lane + 32 < f) e1 = expf(sp[w][lane + 32] - mx);
    float sum = e0 + e1;
#pragma unroll
    for (int o = 16; o; o >>= 1) sum += __shfl_xor_sync(0xffffffffu, sum, o);
    if (lane < f)      sp[w][lane] = e0;
    if (lane + 32 < f) sp[w][lane + 32] = e1;
    __syncwarp();
    float inv = 1.f / sum;
    const float* cvp = qp + 1024;
    float a0 = 0.f, a1 = 0.f;
    for (int l = 0; l < OBS; l++) {
        float p = sp[w][l];
        float2 vf = __bfloat1622float2(*(const __nv_bfloat162*)(ob + 512 + (size_t)l * NB * 1024));
        a0 += p * vf.x;
        a1 += p * vf.y;
    }
    for (int l = 0; l < fr; l++) {
        float p = sp[w][OBS + l];
        float2 vf = __bfloat1622float2(*(const __nv_bfloat162*)(rb + 512 + (size_t)l * BMT * 1024));
        a0 += p * vf.x;
        a1 += p * vf.y;
    }
    float* op = g_ctx + (size_t)bm * 512 + off;
    *(float2*)op = make_float2(cvp[2 * lane] + a0 * inv, cvp[2 * lane + 1] + a1 * inv);
}

// ------------------ layernorm over 512: out = LN(x1+x2+x3)*g+b --------------------
__global__ void k_ln(const float* __restrict__ x1, const float* __restrict__ x2,
                     const float* __restrict__ x3,
                     const float* __restrict__ g, const float* __restrict__ bb,
                     float* __restrict__ out)
{
    int row = blockIdx.x, tid = threadIdx.x;
    __shared__ float red[256];
    size_t base = (size_t)row * 512;
    float v0 = x1[base + tid]       + x2[base + tid]       + x3[base + tid];
    float v1 = x1[base + tid + 256] + x2[base + tid + 256] + x3[base + tid + 256];
    red[tid] = v0 + v1;
    __syncthreads();
    for (int s = 128; s; s >>= 1) { if (tid < s) red[tid] += red[tid + s]; __syncthreads(); }
    float mu = red[0] * (1.f / 512.f);
    __syncthreads();
    float d0 = v0 - mu, d1 = v1 - mu;
    red[tid] = d0 * d0 + d1 * d1;
    __syncthreads();
    for (int s = 128; s; s >>= 1) { if (tid < s) red[tid] += red[tid + s]; __syncthreads(); }
    float rs = rsqrtf(red[0] * (1.f / 512.f) + 1e-5f);
    out[base + tid]       = d0 * rs * g[tid] + bb[tid];
    out[base + tid + 256] = d1 * rs * g[tid + 256] + bb[tid + 256];
}

// ---- fused per-step epilogue: out + emb + prep for step f+1 ---------------------
__global__ void k_step(const float* __restrict__ Wout, const float* __restrict__ bout,
                       const float* __restrict__ Wemb, const float* __restrict__ bemb,
                       const float* __restrict__ loc, const float* __restrict__ feat,
                       const float* __restrict__ Wfus,
                       float* __restrict__ dout, int f)
{
    int bm = blockIdx.x, tid = threadIdx.x;
    int b = bm & 255, m = bm >> 8;
    __shared__ float r0[128], r1[128];
    __shared__ float se[32], ex[32];

    // out = (fus + fusb) @ W_out + b_out
    float s0 = 0.f, s1 = 0.f;
    const float* fp  = g_fus  + (size_t)bm * 448;
    const float* fpb = g_fusb + (size_t)bm * 448;
    for (int c = tid; c < 448; c += 128) {
        float v = fp[c] + fpb[c];
        s0 += v * Wout[c * 2 + 0];
        s1 += v * Wout[c * 2 + 1];
    }
    r0[tid] = s0; r1[tid] = s1;
    __syncthreads();
    for (int s = 64; s; s >>= 1) {
        if (tid < s) { r0[tid] += r0[tid + s]; r1[tid] += r1[tid + s]; }
        __syncthreads();
    }
    float o0 = r0[0] + bout[0];
    float o1 = r1[0] + bout[1];

    // emb_new = relu(out @ W_emb + b_emb)
    if (tid < 32) {
        float e = fmaxf(o0 * Wemb[tid] + o1 * Wemb[32 + tid] + bemb[tid], 0.f);
        se[tid] = e;
        g_emb[bm * 32 + tid] = e;
    }
    if (tid == 0) {
        g_last[bm * 2 + 0] = o0;
        g_last[bm * 2 + 1] = o1;
        int t = f - OBS;
        dout[b * (NM * HOR * 2) + m * (HOR * 2) + t * 2 + 0] = o0;
        dout[b * (NM * HOR * 2) + m * (HOR * 2) + t * 2 + 1] = o1;
    }
    __syncthreads();

    // prep for next step
    int fn = f + 1;
    if (fn < OBS + HOR) {
        float gx = loc[(b * NM + m) * 2 + 0], gy = loc[(b * NM + m) * 2 + 1];
        float dx = gx - o0, dy = gy - o1;
        float t = (float)fn;
        if (tid < 32) {
            float v;
            if (tid < 8)       v = (tid & 1) ? gy : gx;
            else if (tid < 16) v = (tid & 1) ? o1 : o0;
            else if (tid < 24) v = (tid & 1) ? dy : dx;
            else               v = t;
            ex[tid] = v;
            g_E[bm * 64 + tid] = v;
            g_E[bm * 64 + 32 + tid] = se[tid];
        }
        __syncthreads();
        for (int c = tid; c < 512; c += 128) {
            float v;
            if (c < 32)      v = se[c];
            else if (c < 64) v = ex[c - 32];
            else             v = feat[b * INC + (c - 64)];
            g_xlast[bm * 512 + c] = v;
        }
        for (int c = tid; c < 448; c += 128) {
            float v = g_cffus[b * 448 + c];
            v += o0 * Wfus[(512 + 0) * 448 + c];
            v += o1 * Wfus[(512 + 1) * 448 + c];
            v += gx * Wfus[(512 + 2) * 448 + c];
            v += gy * Wfus[(512 + 3) * 448 + c];
            v += dx * Wfus[(512 + 4) * 448 + c];
            v += dy * Wfus[(512 + 5) * 448 + c];
            v += t  * Wfus[(512 + 6) * 448 + c];
            g_rowfus[bm * 448 + c] = v;
        }
    }
}

// ----------------------------------- launch ---------------------------------------
extern "C" void kernel_launch(void* const* d_in, const int* in_sizes, int n_in,
                              void* d_out, int out_size)
{
    const float* feat = (const float*)d_in[0];
    const float* loc  = (const float*)d_in[1];
    const float* obs  = (const float*)d_in[2];
    const float* Wemb = (const float*)d_in[3];
    const float* bemb = (const float*)d_in[4];
    const float* Wqkv = (const float*)d_in[5];
    const float* bqkv = (const float*)d_in[6];
    const float* Wo   = (const float*)d_in[7];
    const float* bo   = (const float*)d_in[8];
    const float* Wff1 = (const float*)d_in[9];
    const float* bff1 = (const float*)d_in[10];
    const float* Wff2 = (const float*)d_in[11];
    const float* bff2 = (const float*)d_in[12];
    const float* ln1g = (const float*)d_in[13];
    const float* ln1b = (const float*)d_in[14];
    const float* ln2g = (const float*)d_in[15];
    const float* ln2b = (const float*)d_in[16];
    const float* Wfus = (const float*)d_in[17];
    const float* bfus = (const float*)d_in[18];
    const float* Wout = (const float*)d_in[19];
    const float* bout = (const float*)d_in[20];
    float* outp = (float*)d_out;

    float *cfeat, *cffus, *Wcat, *eobs, *E, *xlast, *rowfus, *QKVC, *ctx,
          *wo, *wob, *h1, *ff1, *ff2, *ff2b, *h2, *fus, *fusb, *emb;
    __nv_bfloat16 *eKV, *eKVo;
    cudaGetSymbolAddress((void**)&cfeat,  g_cfeat);
    cudaGetSymbolAddress((void**)&cffus,  g_cffus);
    cudaGetSymbolAddress((void**)&Wcat,   g_Wcat);
    cudaGetSymbolAddress((void**)&eobs,   g_eobs);
    cudaGetSymbolAddress((void**)&eKV,    g_eKV);
    cudaGetSymbolAddress((void**)&eKVo,   g_eKVo);
    cudaGetSymbolAddress((void**)&E,      g_E);
    cudaGetSymbolAddress((void**)&xlast,  g_xlast);
    cudaGetSymbolAddress((void**)&rowfus, g_rowfus);
    cudaGetSymbolAddress((void**)&QKVC,   g_QKVC);
    cudaGetSymbolAddress((void**)&ctx,    g_ctx);
    cudaGetSymbolAddress((void**)&wo,     g_wo);
    cudaGetSymbolAddress((void**)&wob,    g_wob);
    cudaGetSymbolAddress((void**)&h1,     g_h1);
    cudaGetSymbolAddress((void**)&ff1,    g_ff1);
    cudaGetSymbolAddress((void**)&ff2,    g_ff2);
    cudaGetSymbolAddress((void**)&ff2b,   g_ff2b);
    cudaGetSymbolAddress((void**)&h2,     g_h2);
    cudaGetSymbolAddress((void**)&fus,    g_fus);
    cudaGetSymbolAddress((void**)&fusb,   g_fusb);
    cudaGetSymbolAddress((void**)&emb,    g_emb);

    const float* NUL = (const float*)0;

    // one-time precompute (inside the graph; cheap + deterministic)
    k_wcat<<<(64 * 1536 + 255) / 256, 256>>>(Wqkv);
    // cfeat = feat @ W_qkv[64:512,:] + b_qkv   (256 x 1536, K=448)
    k_gemm<<<dim3(24, 2), 256>>>(feat, 448, Wqkv + 64 * 1536, 1536,
                                 cfeat, 1536, 448, bqkv, NUL, 1, 0, 0, 0, (void*)0);
    // cffus = feat @ W_fus[519:967,:] + b_fus  (256 x 448, K=448)
    k_gemm<<<dim3(7, 2), 256>>>(feat, 448, Wfus + 519 * 448, 448,
                                cffus, 448, 448, bfus, NUL, 1, 0, 0, 0, (void*)0);
    // obs embeddings, then eKVo = eobs @ W_qkv[0:32, 512:1536]  (5120 x 1024, K=32, bf16 out)
    k_eobs<<<OBS * NB, 32>>>(obs, Wemb, bemb);
    k_gemm<<<dim3(16, 40), 256>>>(eobs, 32, Wqkv + 512, 1536,
                                  eKVo, 1024, 32, NUL, NUL, 1, 0, 0, 1, (void*)0);
    k_init<<<BMT, 32>>>(obs);
    k_prep<<<BMT, 128>>>(loc, feat, Wfus, OBS);

    for (int f = OBS; f < OBS + HOR; f++) {
        // QKVC = E @ Wcat + cfeat[row % 256]   (1536 x 1536, K=64)
        k_gemm<<<dim3(24, 12), 256>>>(E, 64, Wcat, 1536, QKVC, 1536, 64,
                                      NUL, cfeat, 256, 1536, 0, 0, (void*)0);
        k_attn<<<BMT, 256>>>(f);
        // wo(+wob) = ctx @ W_o + b_o           (1536 x 512, K=512, split-K)
        k_gemm<<<dim3(8, 12, 2), 256>>>(ctx, 512, Wo, 512, wo, 512, 256,
                                        bo, NUL, 1, 0, 0, 0, wob);
        k_ln<<<BMT, 256>>>(xlast, wo, wob, ln1g, ln1b, h1);
        // ff1 = relu(h1 @ W_ff1 + b_ff1)       (1536 x 2048, K=512)
        k_gemm<<<dim3(32, 12), 256>>>(h1, 512, Wff1, 2048, ff1, 2048, 512,
                                      bff1, NUL, 1, 0, 1, 0, (void*)0);
        // ff2(+ff2b) = ff1 @ W_ff2 + b_ff2     (1536 x 512, K=2048, split-K)
        k_gemm<<<dim3(8, 12, 2), 256>>>(ff1, 2048, Wff2, 512, ff2, 512, 1024,
                                        bff2, NUL, 1, 0, 0, 0, ff2b);
        k_ln<<<BMT, 256>>>(h1, ff2, ff2b, ln2g, ln2b, h2);
        // fus(+fusb) = h2 @ W_fus[0:512,:] + rowfus  (1536 x 448, K=512, split-K)
        k_gemm<<<dim3(7, 12, 2), 256>>>(h2, 512, Wfus, 448, fus, 448, 256,
                                        NUL, rowfus, BMT, 448, 0, 0, fusb);
        // fused: out + emb + prep(f+1)
        k_step<<<BMT, 128>>>(Wout, bout, Wemb, bemb, loc, feat, Wfus, outp, f);
        // eKV[f] = emb_new @ W_qkv[0:32, 512:1536]  (1536 x 1024, K=32, bf16 out)
        k_gemm<<<dim3(16, 12), 256>>>(emb, 32, Wqkv + 512, 1536,
                                      eKV + (size_t)(f - OBS) * BMT * 1024, 1024, 32,
                                      NUL, NUL, 1, 0, 0, 1, (void*)0);
    }
    (void)in_sizes; (void)n_in; (void)out_size;
}

// round 6
// speedup vs baseline: 2.5958x; 1.0449x over previous
#include <cuda_runtime.h>
#include <cuda_bf16.h>
#include <math.h>

#define NB    256      // batch
#define NM    6        // goals
#define INC   448
#define EMB   32
#define NHEAD 8
#define DFF   2048
#define OBS   20
#define HOR   30
#define DD    512      // model dim
#define LBUF  50
#define HD    64
#define BMT   1536     // NB*NM

// ------------------------- scratch (static device globals) -------------------------
__device__ __align__(256) float g_cfeat[NB*1536];      // feat @ W_qkv[64:512] + b_qkv
__device__ __align__(256) float g_cffus[NB*448];       // feat @ W_fus[519:967] + b_fus
__device__ __align__(256) float g_Wcat[64*1536];       // tf32-rounded
__device__ __align__(256) float g_Wor[512*512];        // tf32-rounded W_o
__device__ __align__(256) float g_Wff1r[512*2048];     // tf32-rounded W_ff1
__device__ __align__(256) float g_Wff2r[2048*512];     // tf32-rounded W_ff2
__device__ __align__(256) float g_Wfusr[512*448];      // tf32-rounded W_fus[0:512]
__device__ __align__(256) float g_eobs[OBS*NB*32];     // relu(obs @ W_emb + b) per (l,b)
__device__ __align__(256) __nv_bfloat16 g_eKVo[(size_t)OBS*NB*1024];   // obs eKV, per-b
__device__ __align__(256) __nv_bfloat16 g_eKV[(size_t)HOR*BMT*1024];   // rollout eKV, per-bm
__device__ __align__(256) float g_E[BMT*64];           // [extras(32) | embPrev(32)] tf32-rounded
__device__ __align__(256) float g_xlast[BMT*DD];
__device__ __align__(256) float g_rowfus[BMT*448];
__device__ __align__(256) float g_QKVC[BMT*1536];      // q | ck | cv
__device__ __align__(256) float g_ctx[BMT*DD];         // tf32-rounded
__device__ __align__(256) float g_wo[BMT*DD];
__device__ __align__(256) float g_wob[BMT*DD];
__device__ __align__(256) float g_h1[BMT*DD];          // tf32-rounded
__device__ __align__(256) float g_ff1[BMT*DFF];        // tf32-rounded
__device__ __align__(256) float g_ff2[BMT*DD];
__device__ __align__(256) float g_ff2b[BMT*DD];
__device__ __align__(256) float g_h2[BMT*DD];          // tf32-rounded
__device__ __align__(256) float g_fus[BMT*448];
__device__ __align__(256) float g_fusb[BMT*448];
__device__ __align__(256) float g_emb[BMT*EMB];        // emb of frame f-1
__device__ __align__(256) float g_last[BMT*2];

// --------------------------- TF32 helpers ----------------------------------------
__device__ __forceinline__ unsigned f2tf(float x) {
    unsigned u;
    asm("cvt.rna.tf32.f32 %0, %1;" : "=r"(u) : "f"(x));
    return u;
}
__device__ __forceinline__ float tfr(float x) { return __uint_as_float(f2tf(x)); }

__device__ __forceinline__ void mma8(float* d, const unsigned* a, const unsigned* b) {
    asm volatile(
        "mma.sync.aligned.m16n8k8.row.col.f32.tf32.tf32.f32 "
        "{%0,%1,%2,%3}, {%4,%5,%6,%7}, {%8,%9}, {%0,%1,%2,%3};"
        : "+f"(d[0]), "+f"(d[1]), "+f"(d[2]), "+f"(d[3])
        : "r"(a[0]), "r"(a[1]), "r"(a[2]), "r"(a[3]), "r"(b[0]), "r"(b[1]));
}

// =============== pipelined TF32 GEMM (cp.async double-buffer) =====================
// Operands MUST already be tf32-rounded (MMA consumes raw fp32 bits, lossless).
// Block tile 128 x NT (NT=128 or 64), BK=32, 256 threads.
// gridDim.z==2 -> split-K: z=1 does upper half into C2 (no bias/rowadd).
template<int NT>
__global__ void k_gemmp(const float* __restrict__ A, int lda,
                        const float* __restrict__ Bm, int ldb,
                        float* __restrict__ C, int ldc, int K,
                        const float* __restrict__ bias,
                        const float* __restrict__ rowadd, int ramod, int ldra,
                        int relu, int otf32, float* __restrict__ C2)
{
    constexpr int BPAD = NT + 4;
    constexpr int ASZ = 128 * 36;
    constexpr int BSZ = 32 * BPAD;
    extern __shared__ float sm[];
    float* AsB = sm;            // 2 stages
    float* BsB = sm + 2 * ASZ;  // 2 stages

    if (blockIdx.z) { A += K; Bm += (size_t)K * ldb; C = C2; bias = 0; rowadd = 0; }

    const int row0 = blockIdx.y * 128, col0 = blockIdx.x * NT;
    const int tid = threadIdx.x, warp = tid >> 5, lane = tid & 31;
    constexpr int WN = (NT == 128) ? 4 : 2;   // warps along n
    constexpr int MI = (NT == 128) ? 4 : 2;   // 16-row m-frags per warp
    const int wm = warp / WN, wn = warp % WN;
    const int l4 = lane >> 2, lm4 = lane & 3;
    const int ar = tid >> 3, akq = (tid & 7) * 4;
    constexpr int NSEG = NT / 4;              // float4 per B row
    constexpr int BIT = 32 * NSEG / 256;      // B cp.async per thread
    const int brow0 = tid / NSEG, bc4 = (tid % NSEG) * 4;

    float acc[MI][4][4] = {};

    auto load = [&](int k0, int s) {
        float* as = AsB + s * ASZ;
        float* bs = BsB + s * BSZ;
#pragma unroll
        for (int i = 0; i < 4; i++) {
            unsigned d = (unsigned)__cvta_generic_to_shared(as + (ar + i * 32) * 36 + akq);
            const float* g = A + (size_t)(row0 + ar + i * 32) * lda + k0 + akq;
            asm volatile("cp.async.cg.shared.global [%0],[%1],16;\n" :: "r"(d), "l"(g));
        }
#pragma unroll
        for (int i = 0; i < BIT; i++) {
            int row = brow0 + i * (256 / NSEG);
            unsigned d = (unsigned)__cvta_generic_to_shared(bs + row * BPAD + bc4);
            const float* g = Bm + (size_t)(k0 + row) * ldb + col0 + bc4;
            asm volatile("cp.async.cg.shared.global [%0],[%1],16;\n" :: "r"(d), "l"(g));
        }
        asm volatile("cp.async.commit_group;\n");
    };

    load(0, 0);
    int stage = 0;
    for (int k0 = 0; k0 < K; k0 += 32) {
        if (k0 + 32 < K) load(k0 + 32, stage ^ 1);
        else             asm volatile("cp.async.commit_group;\n");
        asm volatile("cp.async.wait_group 1;\n");
        __syncthreads();
        const float* as = AsB + stage * ASZ;
        const float* bs = BsB + stage * BSZ;
#pragma unroll
        for (int ks = 0; ks < 4; ks++) {
            const int kk = ks * 8;
            unsigned a[MI][4], b[4][2];
#pragma unroll
            for (int mi = 0; mi < MI; mi++) {
                int mb = wm * (MI * 16) + mi * 16 + l4;
                a[mi][0] = __float_as_uint(as[mb * 36 + kk + lm4]);
                a[mi][1] = __float_as_uint(as[(mb + 8) * 36 + kk + lm4]);
                a[mi][2] = __float_as_uint(as[mb * 36 + kk + lm4 + 4]);
                a[mi][3] = __float_as_uint(as[(mb + 8) * 36 + kk + lm4 + 4]);
            }
#pragma unroll
            for (int nj = 0; nj < 4; nj++) {
                int nb = wn * 32 + nj * 8 + l4;
                b[nj][0] = __float_as_uint(bs[(kk + lm4) * BPAD + nb]);
                b[nj][1] = __float_as_uint(bs[(kk + lm4 + 4) * BPAD + nb]);
            }
#pragma unroll
            for (int mi = 0; mi < MI; mi++)
#pragma unroll
                for (int nj = 0; nj < 4; nj++)
                    mma8(acc[mi][nj], a[mi], b[nj]);
        }
        __syncthreads();
        stage ^= 1;
    }

    // epilogue
#pragma unroll
    for (int mi = 0; mi < MI; mi++) {
        const int rb = row0 + wm * (MI * 16) + mi * 16 + l4;
#pragma unroll
        for (int nj = 0; nj < 4; nj++) {
            const int c = col0 + wn * 32 + nj * 8 + lm4 * 2;
#pragma unroll
            for (int h = 0; h < 2; h++) {
                const int r = rb + h * 8;
                float v0 = acc[mi][nj][h * 2 + 0];
                float v1 = acc[mi][nj][h * 2 + 1];
                if (bias) { v0 += bias[c]; v1 += bias[c + 1]; }
                if (rowadd) {
                    const float* ra = rowadd + (size_t)(r % ramod) * ldra + c;
                    v0 += ra[0]; v1 += ra[1];
                }
                if (relu) { v0 = fmaxf(v0, 0.f); v1 = fmaxf(v1, 0.f); }
                if (otf32) { v0 = tfr(v0); v1 = tfr(v1); }
                *(float2*)(C + (size_t)r * ldc + c) = make_float2(v0, v1);
            }
        }
    }
}

// --------------- legacy TF32 GEMM (converts in-kernel; setup + eKV paths) ---------
__global__ void k_gemm0(const float* __restrict__ A, int lda,
                        const float* __restrict__ Bm, int ldb,
                        void* __restrict__ Cv, int ldc, int K,
                        const float* __restrict__ bias, int obf16)
{
    __shared__ __align__(16) unsigned As[128 * 36];
    __shared__ __align__(16) unsigned Bs[32 * 68];
    const int row0 = blockIdx.y * 128, col0 = blockIdx.x * 64;
    const int tid = threadIdx.x;
    const int warp = tid >> 5, lane = tid & 31;
    const int wm = warp >> 1, wn = warp & 1;
    const int l4 = lane >> 2, lm4 = lane & 3;
    const int ar = tid >> 3, akq = (tid & 7) * 4;
    const int br = tid >> 4, bcq = (tid & 15) * 4;

    float acc[2][4][4] = {};
    float4 pa[4], pb[2];
#pragma unroll
    for (int it = 0; it < 4; it++)
        pa[it] = *(const float4*)(A + (size_t)(row0 + ar + it * 32) * lda + akq);
#pragma unroll
    for (int it = 0; it < 2; it++)
        pb[it] = *(const float4*)(Bm + (size_t)(br + it * 16) * ldb + col0 + bcq);

    for (int k0 = 0; k0 < K; k0 += 32) {
#pragma unroll
        for (int it = 0; it < 4; it++) {
            unsigned* p = &As[(ar + it * 32) * 36 + akq];
            p[0] = f2tf(pa[it].x); p[1] = f2tf(pa[it].y);
            p[2] = f2tf(pa[it].z); p[3] = f2tf(pa[it].w);
        }
#pragma unroll
        for (int it = 0; it < 2; it++) {
            unsigned* p = &Bs[(br + it * 16) * 68 + bcq];
            p[0] = f2tf(pb[it].x); p[1] = f2tf(pb[it].y);
            p[2] = f2tf(pb[it].z); p[3] = f2tf(pb[it].w);
        }
        __syncthreads();
        if (k0 + 32 < K) {
#pragma unroll
            for (int it = 0; it < 4; it++)
                pa[it] = *(const float4*)(A + (size_t)(row0 + ar + it * 32) * lda + k0 + 32 + akq);
#pragma unroll
            for (int it = 0; it < 2; it++)
                pb[it] = *(const float4*)(Bm + (size_t)(k0 + 32 + br + it * 16) * ldb + col0 + bcq);
        }
#pragma unroll
        for (int ks = 0; ks < 4; ks++) {
            const int kk = ks * 8;
            unsigned a[2][4], b[4][2];
#pragma unroll
            for (int mi = 0; mi < 2; mi++) {
                int mb = wm * 32 + mi * 16 + l4;
                a[mi][0] = As[mb * 36 + kk + lm4];
                a[mi][1] = As[(mb + 8) * 36 + kk + lm4];
                a[mi][2] = As[mb * 36 + kk + lm4 + 4];
                a[mi][3] = As[(mb + 8) * 36 + kk + lm4 + 4];
            }
#pragma unroll
            for (int nj = 0; nj < 4; nj++) {
                int nb = wn * 32 + nj * 8 + l4;
                b[nj][0] = Bs[(kk + lm4) * 68 + nb];
                b[nj][1] = Bs[(kk + lm4 + 4) * 68 + nb];
            }
#pragma unroll
            for (int mi = 0; mi < 2; mi++)
#pragma unroll
                for (int nj = 0; nj < 4; nj++)
                    mma8(acc[mi][nj], a[mi], b[nj]);
        }
        __syncthreads();
    }
#pragma unroll
    for (int mi = 0; mi < 2; mi++) {
        const int rb = row0 + wm * 32 + mi * 16 + l4;
#pragma unroll
        for (int nj = 0; nj < 4; nj++) {
            const int c = col0 + wn * 32 + nj * 8 + lm4 * 2;
#pragma unroll
            for (int h = 0; h < 2; h++) {
                const int r = rb + h * 8;
                float v0 = acc[mi][nj][h * 2 + 0];
                float v1 = acc[mi][nj][h * 2 + 1];
                if (bias) { v0 += bias[c]; v1 += bias[c + 1]; }
                if (obf16) {
                    *(__nv_bfloat162*)((__nv_bfloat16*)Cv + (size_t)r * ldc + c) =
                        __floats2bfloat162_rn(v0, v1);
                } else {
                    *(float2*)((float*)Cv + (size_t)r * ldc + c) = make_float2(v0, v1);
                }
            }
        }
    }
}

// ------------------------- one-time small kernels ---------------------------------
__global__ void k_round(const float* __restrict__ s, float* __restrict__ d, int n)
{
    int i = blockIdx.x * 256 + threadIdx.x;
    if (i < n) d[i] = tfr(s[i]);
}

__global__ void k_wcat(const float* __restrict__ Wqkv)
{
    int i = blockIdx.x * blockDim.x + threadIdx.x;
    if (i >= 64 * 1536) return;
    int r = i / 1536, c = i - r * 1536;
    float v;
    if (r < 32) v = Wqkv[(32 + r) * 1536 + c];
    else        v = (c < 512) ? Wqkv[(r - 32) * 1536 + c] : 0.f;
    g_Wcat[i] = tfr(v);
}

__global__ void k_eobs(const float* __restrict__ obs, const float* __restrict__ Wemb,
                       const float* __restrict__ bemb)
{
    int r = blockIdx.x, t = threadIdx.x;   // r = l*NB + b, t < 32
    float o0 = obs[r * 2 + 0], o1 = obs[r * 2 + 1];
    g_eobs[r * 32 + t] = fmaxf(o0 * Wemb[t] + o1 * Wemb[32 + t] + bemb[t], 0.f);
}

__global__ void k_init(const float* __restrict__ obs)
{
    int bm = blockIdx.x, t = threadIdx.x;
    int b = bm & 255;
    g_emb[bm * 32 + t] = g_eobs[((OBS - 1) * NB + b) * 32 + t];
    if (t < 2) g_last[bm * 2 + t] = obs[((OBS - 1) * NB + b) * 2 + t];
}

// ------------------------- initial prep (f = OBS only) ----------------------------
__global__ void k_prep(const float* __restrict__ loc, const float* __restrict__ feat,
                       const float* __restrict__ Wfus, int f)
{
    int bm = blockIdx.x, tid = threadIdx.x;
    int b = bm & 255, m = bm >> 8;
    float gx = loc[(b * NM + m) * 2 + 0], gy = loc[(b * NM + m) * 2 + 1];
    float lx = g_last[bm * 2 + 0], ly = g_last[bm * 2 + 1];
    float dx = gx - lx, dy = gy - ly;
    float t = (float)f;
    __shared__ float ex[32];
    if (tid < 32) {
        float v;
        if (tid < 8)       v = (tid & 1) ? gy : gx;
        else if (tid < 16) v = (tid & 1) ? ly : lx;
        else if (tid < 24) v = (tid & 1) ? dy : dx;
        else               v = t;
        ex[tid] = v;
        g_E[bm * 64 + tid] = tfr(v);
        g_E[bm * 64 + 32 + tid] = tfr(g_emb[bm * 32 + tid]);
    }
    __syncthreads();
    for (int c = tid; c < 512; c += 128) {
        float v;
        if (c < 32)      v = g_emb[bm * 32 + c];
        else if (c < 64) v = ex[c - 32];
        else             v = feat[b * INC + (c - 64)];
        g_xlast[bm * 512 + c] = v;
    }
    for (int c = tid; c < 448; c += 128) {
        float v = g_cffus[b * 448 + c];
        v += lx * Wfus[(512 + 0) * 448 + c];
        v += ly * Wfus[(512 + 1) * 448 + c];
        v += gx * Wfus[(512 + 2) * 448 + c];
        v += gy * Wfus[(512 + 3) * 448 + c];
        v += dx * Wfus[(512 + 4) * 448 + c];
        v += dy * Wfus[(512 + 5) * 448 + c];
        v += t  * Wfus[(512 + 6) * 448 + c];
        g_rowfus[bm * 448 + c] = v;
    }
}

// ------------------------- per-step attention -------------------------------------
__global__ void k_attn(int f)
{
    int bm = blockIdx.x;
    int tid = threadIdx.x, w = tid >> 5, lane = tid & 31;
    int b = bm & 255;
    const float* qp = g_QKVC + (size_t)bm * 1536 + w * 64;
    float q0 = qp[2 * lane], q1 = qp[2 * lane + 1];
    const float* ckp = qp + 512;
    float s = q0 * ckp[2 * lane] + q1 * ckp[2 * lane + 1];
#pragma unroll
    for (int o = 16; o; o >>= 1) s += __shfl_xor_sync(0xffffffffu, s, o);
    const float qdot = s;
    __shared__ float sp[8][56];
    const int off = w * 64 + 2 * lane;
    const __nv_bfloat16* ob = g_eKVo + (size_t)b * 1024 + off;
    const __nv_bfloat16* rb = g_eKV + (size_t)bm * 1024 + off;
    const int fr = f - OBS;
    for (int l = 0; l < OBS; l++) {
        float2 kf = __bfloat1622float2(*(const __nv_bfloat162*)(ob + (size_t)l * NB * 1024));
        float d = q0 * kf.x + q1 * kf.y;
#pragma unroll
        for (int o = 16; o; o >>= 1) d += __shfl_xor_sync(0xffffffffu, d, o);
        if (lane == 0) sp[w][l] = (d + qdot) * 0.125f;
    }
    for (int l = 0; l < fr; l++) {
        float2 kf = __bfloat1622float2(*(const __nv_bfloat162*)(rb + (size_t)l * BMT * 1024));
        float d = q0 * kf.x + q1 * kf.y;
#pragma unroll
        for (int o = 16; o; o >>= 1) d += __shfl_xor_sync(0xffffffffu, d, o);
        if (lane == 0) sp[w][OBS + l] = (d + qdot) * 0.125f;
    }
    __syncwarp();
    float mx = -1e30f;
    if (lane < f)      mx = sp[w][lane];
    if (lane + 32 < f) mx = fmaxf(mx, sp[w][lane + 32]);
#pragma unroll
    for (int o = 16; o; o >>= 1) mx = fmaxf(mx, __shfl_xor_sync(0xffffffffu, mx, o));
    float e0 = 0.f, e1 = 0.f;
    if (lane < f)      e0 = expf(sp[w][lane] - mx);
    if (lane + 32 < f) e1 = expf(sp[w][lane + 32] - mx);
    float sum = e0 + e1;
#pragma unroll
    for (int o = 16; o; o >>= 1) sum += __shfl_xor_sync(0xffffffffu, sum, o);
    if (lane < f)      sp[w][lane] = e0;
    if (lane + 32 < f) sp[w][lane + 32] = e1;
    __syncwarp();
    float inv = 1.f / sum;
    const float* cvp = qp + 1024;
    float a0 = 0.f, a1 = 0.f;
    for (int l = 0; l < OBS; l++) {
        float p = sp[w][l];
        float2 vf = __bfloat1622float2(*(const __nv_bfloat162*)(ob + 512 + (size_t)l * NB * 1024));
        a0 += p * vf.x;
        a1 += p * vf.y;
    }
    for (int l = 0; l < fr; l++) {
        float p = sp[w][OBS + l];
        float2 vf = __bfloat1622float2(*(const __nv_bfloat162*)(rb + 512 + (size_t)l * BMT * 1024));
        a0 += p * vf.x;
        a1 += p * vf.y;
    }
    float* op = g_ctx + (size_t)bm * 512 + off;
    *(float2*)op = make_float2(tfr(cvp[2 * lane] + a0 * inv),
                               tfr(cvp[2 * lane + 1] + a1 * inv));
}

// ------------------ layernorm over 512: out = tf32(LN(x1+x2+x3)*g+b) --------------
__global__ void k_ln(const float* __restrict__ x1, const float* __restrict__ x2,
                     const float* __restrict__ x3,
                     const float* __restrict__ g, const float* __restrict__ bb,
                     float* __restrict__ out)
{
    int row = blockIdx.x, tid = threadIdx.x;
    __shared__ float red[256];
    size_t base = (size_t)row * 512;
    float v0 = x1[base + tid]       + x2[base + tid]       + x3[base + tid];
    float v1 = x1[base + tid + 256] + x2[base + tid + 256] + x3[base + tid + 256];
    red[tid] = v0 + v1;
    __syncthreads();
    for (int s = 128; s; s >>= 1) { if (tid < s) red[tid] += red[tid + s]; __syncthreads(); }
    float mu = red[0] * (1.f / 512.f);
    __syncthreads();
    float d0 = v0 - mu, d1 = v1 - mu;
    red[tid] = d0 * d0 + d1 * d1;
    __syncthreads();
    for (int s = 128; s; s >>= 1) { if (tid < s) red[tid] += red[tid + s]; __syncthreads(); }
    float rs = rsqrtf(red[0] * (1.f / 512.f) + 1e-5f);
    out[base + tid]       = tfr(d0 * rs * g[tid] + bb[tid]);
    out[base + tid + 256] = tfr(d1 * rs * g[tid + 256] + bb[tid + 256]);
}

// ---- fused per-step epilogue: out + emb + prep for step f+1 ---------------------
__global__ void k_step(const float* __restrict__ Wout, const float* __restrict__ bout,
                       const float* __restrict__ Wemb, const float* __restrict__ bemb,
                       const float* __restrict__ loc, const float* __restrict__ feat,
                       const float* __restrict__ Wfus,
                       float* __restrict__ dout, int f)
{
    int bm = blockIdx.x, tid = threadIdx.x;
    int b = bm & 255, m = bm >> 8;
    __shared__ float r0[128], r1[128];
    __shared__ float se[32], ex[32];

    float s0 = 0.f, s1 = 0.f;
    const float* fp  = g_fus  + (size_t)bm * 448;
    const float* fpb = g_fusb + (size_t)bm * 448;
    for (int c = tid; c < 448; c += 128) {
        float v = fp[c] + fpb[c];
        s0 += v * Wout[c * 2 + 0];
        s1 += v * Wout[c * 2 + 1];
    }
    r0[tid] = s0; r1[tid] = s1;
    __syncthreads();
    for (int s = 64; s; s >>= 1) {
        if (tid < s) { r0[tid] += r0[tid + s]; r1[tid] += r1[tid + s]; }
        __syncthreads();
    }
    float o0 = r0[0] + bout[0];
    float o1 = r1[0] + bout[1];

    if (tid < 32) {
        float e = fmaxf(o0 * Wemb[tid] + o1 * Wemb[32 + tid] + bemb[tid], 0.f);
        se[tid] = e;
        g_emb[bm * 32 + tid] = e;
    }
    if (tid == 0) {
        g_last[bm * 2 + 0] = o0;
        g_last[bm * 2 + 1] = o1;
        int t = f - OBS;
        dout[b * (NM * HOR * 2) + m * (HOR * 2) + t * 2 + 0] = o0;
        dout[b * (NM * HOR * 2) + m * (HOR * 2) + t * 2 + 1] = o1;
    }
    __syncthreads();

    int fn = f + 1;
    if (fn < OBS + HOR) {
        float gx = loc[(b * NM + m) * 2 + 0], gy = loc[(b * NM + m) * 2 + 1];
        float dx = gx - o0, dy = gy - o1;
        float t = (float)fn;
        if (tid < 32) {
            float v;
            if (tid < 8)       v = (tid & 1) ? gy : gx;
            else if (tid < 16) v = (tid & 1) ? o1 : o0;
            else if (tid < 24) v = (tid & 1) ? dy : dx;
            else               v = t;
            ex[tid] = v;
            g_E[bm * 64 + tid] = tfr(v);
            g_E[bm * 64 + 32 + tid] = tfr(se[tid]);
        }
        __syncthreads();
        for (int c = tid; c < 512; c += 128) {
            float v;
            if (c < 32)      v = se[c];
            else if (c < 64) v = ex[c - 32];
            else             v = feat[b * INC + (c - 64)];
            g_xlast[bm * 512 + c] = v;
        }
        for (int c = tid; c < 448; c += 128) {
            float v = g_cffus[b * 448 + c];
            v += o0 * Wfus[(512 + 0) * 448 + c];
            v += o1 * Wfus[(512 + 1) * 448 + c];
            v += gx * Wfus[(512 + 2) * 448 + c];
            v += gy * Wfus[(512 + 3) * 448 + c];
            v += dx * Wfus[(512 + 4) * 448 + c];
            v += dy * Wfus[(512 + 5) * 448 + c];
            v += t  * Wfus[(512 + 6) * 448 + c];
            g_rowfus[bm * 448 + c] = v;
        }
    }
}

// ----------------------------------- launch ---------------------------------------
extern "C" void kernel_launch(void* const* d_in, const int* in_sizes, int n_in,
                              void* d_out, int out_size)
{
    const float* feat = (const float*)d_in[0];
    const float* loc  = (const float*)d_in[1];
    const float* obs  = (const float*)d_in[2];
    const float* Wemb = (const float*)d_in[3];
    const float* bemb = (const float*)d_in[4];
    const float* Wqkv = (const float*)d_in[5];
    const float* bqkv = (const float*)d_in[6];
    const float* Wo   = (const float*)d_in[7];
    const float* bo   = (const float*)d_in[8];
    const float* Wff1 = (const float*)d_in[9];
    const float* bff1 = (const float*)d_in[10];
    const float* Wff2 = (const float*)d_in[11];
    const float* bff2 = (const float*)d_in[12];
    const float* ln1g = (const float*)d_in[13];
    const float* ln1b = (const float*)d_in[14];
    const float* ln2g = (const float*)d_in[15];
    const float* ln2b = (const float*)d_in[16];
    const float* Wfus = (const float*)d_in[17];
    const float* bfus = (const float*)d_in[18];
    const float* Wout = (const float*)d_in[19];
    const float* bout = (const float*)d_in[20];
    float* outp = (float*)d_out;

    float *cfeat, *cffus, *Wcat, *Wor, *Wff1r, *Wff2r, *Wfusr, *eobs, *E, *xlast,
          *rowfus, *QKVC, *ctx, *wo, *wob, *h1, *ff1, *ff2, *ff2b, *h2, *fus,
          *fusb, *emb;
    __nv_bfloat16 *eKV, *eKVo;
    cudaGetSymbolAddress((void**)&cfeat,  g_cfeat);
    cudaGetSymbolAddress((void**)&cffus,  g_cffus);
    cudaGetSymbolAddress((void**)&Wcat,   g_Wcat);
    cudaGetSymbolAddress((void**)&Wor,    g_Wor);
    cudaGetSymbolAddress((void**)&Wff1r,  g_Wff1r);
    cudaGetSymbolAddress((void**)&Wff2r,  g_Wff2r);
    cudaGetSymbolAddress((void**)&Wfusr,  g_Wfusr);
    cudaGetSymbolAddress((void**)&eobs,   g_eobs);
    cudaGetSymbolAddress((void**)&eKV,    g_eKV);
    cudaGetSymbolAddress((void**)&eKVo,   g_eKVo);
    cudaGetSymbolAddress((void**)&E,      g_E);
    cudaGetSymbolAddress((void**)&xlast,  g_xlast);
    cudaGetSymbolAddress((void**)&rowfus, g_rowfus);
    cudaGetSymbolAddress((void**)&QKVC,   g_QKVC);
    cudaGetSymbolAddress((void**)&ctx,    g_ctx);
    cudaGetSymbolAddress((void**)&wo,     g_wo);
    cudaGetSymbolAddress((void**)&wob,    g_wob);
    cudaGetSymbolAddress((void**)&h1,     g_h1);
    cudaGetSymbolAddress((void**)&ff1,    g_ff1);
    cudaGetSymbolAddress((void**)&ff2,    g_ff2);
    cudaGetSymbolAddress((void**)&ff2b,   g_ff2b);
    cudaGetSymbolAddress((void**)&h2,     g_h2);
    cudaGetSymbolAddress((void**)&fus,    g_fus);
    cudaGetSymbolAddress((void**)&fusb,   g_fusb);
    cudaGetSymbolAddress((void**)&emb,    g_emb);

    const float* NUL = (const float*)0;
    float* FNUL = (float*)0;

    const int SMEM128 = (2 * 128 * 36 + 2 * 32 * 132) * 4;  // 70656
    const int SMEM64  = (2 * 128 * 36 + 2 * 32 * 68) * 4;   // 54272
    cudaFuncSetAttribute(k_gemmp<128>, cudaFuncAttributeMaxDynamicSharedMemorySize, SMEM128);
    cudaFuncSetAttribute(k_gemmp<64>,  cudaFuncAttributeMaxDynamicSharedMemorySize, SMEM64);

    // one-time precompute
    k_wcat<<<(64 * 1536 + 255) / 256, 256>>>(Wqkv);
    k_round<<<(512 * 512  + 255) / 256, 256>>>(Wo,   Wor,   512 * 512);
    k_round<<<(512 * 2048 + 255) / 256, 256>>>(Wff1, Wff1r, 512 * 2048);
    k_round<<<(2048 * 512 + 255) / 256, 256>>>(Wff2, Wff2r, 2048 * 512);
    k_round<<<(512 * 448  + 255) / 256, 256>>>(Wfus, Wfusr, 512 * 448);
    // cfeat = feat @ W_qkv[64:512,:] + b_qkv   (256 x 1536, K=448)
    k_gemm0<<<dim3(24, 2), 256>>>(feat, 448, Wqkv + 64 * 1536, 1536,
                                  cfeat, 1536, 448, bqkv, 0);
    // cffus = feat @ W_fus[519:967,:] + b_fus  (256 x 448, K=448)
    k_gemm0<<<dim3(7, 2), 256>>>(feat, 448, Wfus + 519 * 448, 448,
                                 cffus, 448, 448, bfus, 0);
    k_eobs<<<OBS * NB, 32>>>(obs, Wemb, bemb);
    // eKVo = eobs @ W_qkv[0:32, 512:1536]  (5120 x 1024, K=32, bf16 out)
    k_gemm0<<<dim3(16, 40), 256>>>(eobs, 32, Wqkv + 512, 1536,
                                   eKVo, 1024, 32, NUL, 1);
    k_init<<<BMT, 32>>>(obs);
    k_prep<<<BMT, 128>>>(loc, feat, Wfus, OBS);

    for (int f = OBS; f < OBS + HOR; f++) {
        // QKVC = E @ Wcat + cfeat[row % 256]   (1536 x 1536, K=64)
        k_gemmp<128><<<dim3(12, 12), 256, SMEM128>>>(E, 64, Wcat, 1536, QKVC, 1536, 64,
                                                     NUL, cfeat, 256, 1536, 0, 0, FNUL);
        k_attn<<<BMT, 256>>>(f);
        // wo(+wob) = ctx @ W_o + b_o           (1536 x 512, K=512, split-K)
        k_gemmp<64><<<dim3(8, 12, 2), 256, SMEM64>>>(ctx, 512, Wor, 512, wo, 512, 256,
                                                     bo, NUL, 1, 0, 0, 0, wob);
        k_ln<<<BMT, 256>>>(xlast, wo, wob, ln1g, ln1b, h1);
        // ff1 = tf32(relu(h1 @ W_ff1 + b_ff1)) (1536 x 2048, K=512)
        k_gemmp<128><<<dim3(16, 12), 256, SMEM128>>>(h1, 512, Wff1r, 2048, ff1, 2048, 512,
                                                     bff1, NUL, 1, 0, 1, 1, FNUL);
        // ff2(+ff2b) = ff1 @ W_ff2 + b_ff2     (1536 x 512, K=2048, split-K)
        k_gemmp<64><<<dim3(8, 12, 2), 256, SMEM64>>>(ff1, 2048, Wff2r, 512, ff2, 512, 1024,
                                                     bff2, NUL, 1, 0, 0, 0, ff2b);
        k_ln<<<BMT, 256>>>(h1, ff2, ff2b, ln2g, ln2b, h2);
        // fus(+fusb) = h2 @ W_fus[0:512,:] + rowfus  (1536 x 448, K=512, split-K)
        k_gemmp<64><<<dim3(7, 12, 2), 256, SMEM64>>>(h2, 512, Wfusr, 448, fus, 448, 256,
                                                     NUL, rowfus, BMT, 448, 0, 0, fusb);
        // fused: out + emb + prep(f+1)
        k_step<<<BMT, 128>>>(Wout, bout, Wemb, bemb, loc, feat, Wfus, outp, f);
        // eKV[f] = emb_new @ W_qkv[0:32, 512:1536]  (1536 x 1024, K=32, bf16 out)
        k_gemm0<<<dim3(16, 12), 256>>>(emb, 32, Wqkv + 512, 1536,
                                       eKV + (size_t)(f - OBS) * BMT * 1024, 1024, 32,
                                       NUL, 1);
    }
    (void)in_sizes; (void)n_in; (void)out_size;
}